// round 7
// baseline (speedup 1.0000x reference)
#include <cuda_runtime.h>
#include <cuda_bf16.h>
#include <cstdint>
#include <math.h>

#define BB 2
#define TT 2048
#define HIDDEN 1024
#define NH 16
#define QKV_O 3072   // (16 + 2*16) * 64
#define MROWS (BB*TT) // 4096

// Scratch (allocation-free rule: __device__ globals)
__device__ float g_qkv[(size_t)MROWS * QKV_O];            // [B*T, 3072] fp32
__device__ __nv_bfloat16 g_hs_h[(size_t)MROWS * HIDDEN];
__device__ __nv_bfloat16 g_hs_l[(size_t)MROWS * HIDDEN];
__device__ __nv_bfloat16 g_wq_h[(size_t)QKV_O * HIDDEN];
__device__ __nv_bfloat16 g_wq_l[(size_t)QKV_O * HIDDEN];
__device__ __nv_bfloat16 g_wo_h[(size_t)HIDDEN * HIDDEN];
__device__ __nv_bfloat16 g_wo_l[(size_t)HIDDEN * HIDDEN];
__device__ __nv_bfloat16 g_ctx_h[(size_t)MROWS * HIDDEN];
__device__ __nv_bfloat16 g_ctx_l[(size_t)MROWS * HIDDEN];

// ===========================================================================
// Helpers
// ===========================================================================
__device__ __forceinline__ uint32_t smem_to_u32(const void* p) {
    uint32_t a;
    asm("{ .reg .u64 t; cvta.to.shared.u64 t, %1; cvt.u32.u64 %0, t; }" : "=r"(a) : "l"(p));
    return a;
}
__device__ __forceinline__ void ldsm4(unsigned* r, uint32_t addr) {
    asm volatile("ldmatrix.sync.aligned.m8n8.x4.shared.b16 {%0,%1,%2,%3}, [%4];"
                 : "=r"(r[0]), "=r"(r[1]), "=r"(r[2]), "=r"(r[3]) : "r"(addr));
}
__device__ __forceinline__ void ldsm4t(unsigned* r, uint32_t addr) {
    asm volatile("ldmatrix.sync.aligned.m8n8.x4.trans.shared.b16 {%0,%1,%2,%3}, [%4];"
                 : "=r"(r[0]), "=r"(r[1]), "=r"(r[2]), "=r"(r[3]) : "r"(addr));
}
__device__ __forceinline__ void mma_bf16(float* c, const unsigned* a, unsigned b0, unsigned b1) {
    asm volatile("mma.sync.aligned.m16n8k16.row.col.f32.bf16.bf16.f32 "
                 "{%0,%1,%2,%3}, {%4,%5,%6,%7}, {%8,%9}, {%0,%1,%2,%3};"
                 : "+f"(c[0]), "+f"(c[1]), "+f"(c[2]), "+f"(c[3])
                 : "r"(a[0]), "r"(a[1]), "r"(a[2]), "r"(a[3]), "r"(b0), "r"(b1));
}
__device__ __forceinline__ void split4(float4 v, uint2& hi, uint2& lo)
{
    __nv_bfloat16 h0 = __float2bfloat16_rn(v.x);
    __nv_bfloat16 h1 = __float2bfloat16_rn(v.y);
    __nv_bfloat16 h2 = __float2bfloat16_rn(v.z);
    __nv_bfloat16 h3 = __float2bfloat16_rn(v.w);
    __nv_bfloat16 l0 = __float2bfloat16_rn(v.x - __bfloat162float(h0));
    __nv_bfloat16 l1 = __float2bfloat16_rn(v.y - __bfloat162float(h1));
    __nv_bfloat16 l2 = __float2bfloat16_rn(v.z - __bfloat162float(h2));
    __nv_bfloat16 l3 = __float2bfloat16_rn(v.w - __bfloat162float(h3));
    __nv_bfloat162 hp0(h0, h1), hp1(h2, h3), lp0(l0, l1), lp1(l2, l3);
    hi.x = *(uint32_t*)&hp0; hi.y = *(uint32_t*)&hp1;
    lo.x = *(uint32_t*)&lp0; lo.y = *(uint32_t*)&lp1;
}
__device__ __forceinline__ unsigned pk(float x, float y) {
    __nv_bfloat162 p(__float2bfloat16_rn(x), __float2bfloat16_rn(y));
    return *(unsigned*)&p;
}
__device__ __forceinline__ void splitp(float x, float y, unsigned& h, unsigned& l) {
    __nv_bfloat16 hx = __float2bfloat16_rn(x), hy = __float2bfloat16_rn(y);
    __nv_bfloat16 lx = __float2bfloat16_rn(x - __bfloat162float(hx));
    __nv_bfloat16 ly = __float2bfloat16_rn(y - __bfloat162float(hy));
    __nv_bfloat162 hp(hx, hy), lp(lx, ly);
    h = *(unsigned*)&hp; l = *(unsigned*)&lp;
}
#define CP_ASYNC16(dst, src) \
    asm volatile("cp.async.cg.shared.global [%0], [%1], 16;" :: "r"(dst), "l"(src))
#define CP_COMMIT() asm volatile("cp.async.commit_group;" ::: "memory")
#define CP_WAIT0()  asm volatile("cp.async.wait_group 0;" ::: "memory")

// ===========================================================================
// fp32 -> bf16 hi/lo split (one pass per tensor)
// ===========================================================================
__global__ __launch_bounds__(256) void conv_split(const float* __restrict__ x,
                                                  __nv_bfloat16* __restrict__ hi,
                                                  __nv_bfloat16* __restrict__ lo,
                                                  int n4)
{
    int i = blockIdx.x * blockDim.x + threadIdx.x;
    if (i >= n4) return;
    float4 v = ((const float4*)x)[i];
    uint2 h, l;
    split4(v, h, l);
    ((uint2*)hi)[i] = h;
    ((uint2*)lo)[i] = l;
}

// ===========================================================================
// bf16x3 HMMA GEMM, pre-split inputs, cp.async double-buffered.
// C[M,N] = A[M,K] * B[N,K]^T ; A,B given as hi/lo bf16 row-major.
// 128x128 tile, BK=32, 8 warps (64x32 each).
// ===========================================================================
#define SA 40
#define TSB (128 * SA * 2)        // tile bytes (10240)
#define BUFB (4 * TSB)            // per-buffer bytes (40960)

__global__ __launch_bounds__(256) void gemm_bf16(const __nv_bfloat16* __restrict__ Ah,
                                                 const __nv_bfloat16* __restrict__ Al,
                                                 const __nv_bfloat16* __restrict__ Bh,
                                                 const __nv_bfloat16* __restrict__ Bl,
                                                 float* __restrict__ C,
                                                 int M, int N, int K)
{
    extern __shared__ char dsm[];
    const uint32_t sbase = smem_to_u32(dsm);

    const int tid  = threadIdx.x;
    const int wid  = tid >> 5;
    const int lane = tid & 31;
    const int warp_m = wid >> 2;
    const int warp_n = wid & 3;
    const int bm = blockIdx.y * 128;
    const int bn = blockIdx.x * 128;
    const int lj = lane & 7;
    const int li = lane >> 3;

    float c[4][4][4];
#pragma unroll
    for (int mt = 0; mt < 4; mt++)
#pragma unroll
        for (int nt = 0; nt < 4; nt++)
#pragma unroll
            for (int j = 0; j < 4; j++) c[mt][nt][j] = 0.f;

    const int a_row_base = warp_m * 64 + lj + ((li & 1) << 3);
    const int a_col_base = (li >> 1) << 3;
    const int b_row = warp_n * 32 + li * 8 + lj;

    // async chunk loader: i in 0..7, tile = i>>1 (Ah Al Bh Bl), 512 16B ops/tile
    auto load_chunk = [&](int ch, int buf) {
#pragma unroll
        for (int i = 0; i < 8; i++) {
            const int tile = i >> 1;
            const int v = ((i & 1) << 8) + tid;    // 0..511
            const int r = v >> 2;
            const int c8 = (v & 3) << 3;           // half offset (0,8,16,24)
            const __nv_bfloat16* sp = (tile == 0) ? Ah : (tile == 1) ? Al
                                     : (tile == 2) ? Bh : Bl;
            const int grow = ((tile < 2) ? bm : bn) + r;
            uint32_t dst = sbase + buf * BUFB + tile * TSB + (uint32_t)(r * SA + c8) * 2;
            CP_ASYNC16(dst, sp + (size_t)grow * K + ch * 32 + c8);
        }
        CP_COMMIT();
    };

    const int nchunks = K >> 5;
    load_chunk(0, 0);

    for (int ch = 0; ch < nchunks; ch++) {
        const int buf = ch & 1;
        CP_WAIT0();
        __syncthreads();
        if (ch + 1 < nchunks) load_chunk(ch + 1, buf ^ 1);

        const uint32_t base = sbase + buf * BUFB;
        const uint32_t oAl = TSB, oBh = 2 * TSB, oBl = 3 * TSB;
#pragma unroll
        for (int ks = 0; ks < 2; ks++) {
            const int k0 = ks * 16;
            unsigned bh[2][4], bl[2][4];
#pragma unroll
            for (int kh = 0; kh < 2; kh++) {
                uint32_t ba = base + (uint32_t)(b_row * SA + k0 + kh * 8) * 2;
                ldsm4(bh[kh], oBh + ba);
                ldsm4(bl[kh], oBl + ba);
            }
#pragma unroll
            for (int mt = 0; mt < 4; mt++) {
                unsigned ah[4], al[4];
                uint32_t aa = base + (uint32_t)((a_row_base + mt * 16) * SA + k0 + a_col_base) * 2;
                ldsm4(ah, aa);
                ldsm4(al, oAl + aa);
#pragma unroll
                for (int nt = 0; nt < 4; nt++) {
                    mma_bf16(c[mt][nt], ah, bh[0][nt], bh[1][nt]);
                    mma_bf16(c[mt][nt], ah, bl[0][nt], bl[1][nt]);
                    mma_bf16(c[mt][nt], al, bh[0][nt], bh[1][nt]);
                }
            }
        }
        __syncthreads();
    }

    const int q  = lane >> 2;
    const int t4 = lane & 3;
#pragma unroll
    for (int mt = 0; mt < 4; mt++) {
        int row0 = bm + warp_m * 64 + mt * 16 + q;
#pragma unroll
        for (int nt = 0; nt < 4; nt++) {
            int col = bn + warp_n * 32 + nt * 8 + 2 * t4;
            *(float2*)&C[(size_t)row0 * N + col] =
                make_float2(c[mt][nt][0], c[mt][nt][1]);
            *(float2*)&C[(size_t)(row0 + 8) * N + col] =
                make_float2(c[mt][nt][2], c[mt][nt][3]);
        }
    }
}

// ---------------------------------------------------------------------------
// RoPE in-place on Q and K heads of qkv [B*T, 48, 64].
// ---------------------------------------------------------------------------
__global__ __launch_bounds__(256) void rope_kernel(float* __restrict__ qkv,
                                                   const float* __restrict__ cos_t,
                                                   const float* __restrict__ sin_t)
{
    int idx = blockIdx.x * blockDim.x + threadIdx.x;
    int half = idx & 31;
    int rest = idx >> 5;
    int head = rest & 31;
    int bt   = rest >> 5;
    int t    = bt & (TT - 1);
    float c = cos_t[t * 64 + half];
    float s = sin_t[t * 64 + half];
    size_t base = ((size_t)bt * 48 + head) * 64;
    float x1 = qkv[base + half];
    float x2 = qkv[base + 32 + half];
    qkv[base + half]      = x1 * c - x2 * s;
    qkv[base + 32 + half] = x2 * c + x1 * s;
}

// ===========================================================================
// bf16x3 HMMA flash attention (causal). Block = (64 q-rows, head, batch),
// 4 warps x 16 rows, Bc=64, D=64. Epilogue writes bf16 hi/lo ctx.
// ===========================================================================
#define FSA 72
#define FT (64 * FSA)   // halves per tile

__global__ __launch_bounds__(128) void flash_attn_mma(const float* __restrict__ qkv,
                                                      __nv_bfloat16* __restrict__ ctx_h,
                                                      __nv_bfloat16* __restrict__ ctx_l)
{
    extern __shared__ __nv_bfloat16 sh[];   // Qh Ql Kh Kl Vh Vl  (54 KB)
    const uint32_t sbase = smem_to_u32(sh);
    const uint32_t oQl = FT * 2, oKh = FT * 4, oKl = FT * 6, oVh = FT * 8, oVl = FT * 10;

    const int qt = blockIdx.x;
    const int h  = blockIdx.y;
    const int b  = blockIdx.z;
    const int tid  = threadIdx.x;
    const int wid  = tid >> 5;
    const int lane = tid & 31;
    const int lj = lane & 7;
    const int li = lane >> 3;
    const int g  = lane >> 2;
    const int t4 = lane & 3;
    const int wrow = wid * 16;

#pragma unroll
    for (int i = 0; i < 8; i++) {
        int e = i * 128 + tid;
        int r = e >> 4;
        int c4 = (e & 15) << 2;
        float4 q4 = *(const float4*)&qkv[(((size_t)(b * TT + qt * 64 + r)) * 48 + h) * 64 + c4];
        q4.x *= 0.125f; q4.y *= 0.125f; q4.z *= 0.125f; q4.w *= 0.125f;
        uint2 hv, lv;
        split4(q4, hv, lv);
        uint32_t so = (uint32_t)(r * FSA + c4) * 2;
        *(uint2*)((char*)sh + so) = hv;
        *(uint2*)((char*)sh + oQl + so) = lv;
    }

    float m0 = -1e30f, m1 = -1e30f, l0 = 0.f, l1 = 0.f;
    float o[8][4];
#pragma unroll
    for (int nt = 0; nt < 8; nt++)
#pragma unroll
        for (int j = 0; j < 4; j++) o[nt][j] = 0.f;

    const int a_row = wrow + lj + ((li & 1) << 3);
    const int a_col = (li >> 1) << 3;
    const int b_row = li * 8 + lj;
    const int v_row = lj + ((li & 1) << 3);
    const int v_col = (lane >> 4) << 3;

    __syncthreads();

    for (int kt = 0; kt <= qt; kt++) {
#pragma unroll
        for (int i = 0; i < 8; i++) {
            int e = i * 128 + tid;
            int r = e >> 4;
            int c4 = (e & 15) << 2;
            size_t baseK = (((size_t)(b * TT + kt * 64 + r)) * 48 + NH + h) * 64 + c4;
            uint32_t so = (uint32_t)(r * FSA + c4) * 2;
            uint2 hv, lv;
            split4(*(const float4*)&qkv[baseK], hv, lv);
            *(uint2*)((char*)sh + oKh + so) = hv;
            *(uint2*)((char*)sh + oKl + so) = lv;
            split4(*(const float4*)&qkv[baseK + NH * 64], hv, lv);
            *(uint2*)((char*)sh + oVh + so) = hv;
            *(uint2*)((char*)sh + oVl + so) = lv;
        }
        __syncthreads();

        float s[8][4];
#pragma unroll
        for (int nt = 0; nt < 8; nt++)
#pragma unroll
            for (int j = 0; j < 4; j++) s[nt][j] = 0.f;

#pragma unroll
        for (int ks = 0; ks < 4; ks++) {
            const int k0 = ks * 16;
            unsigned ah[4], al[4];
            uint32_t aa = sbase + (uint32_t)(a_row * FSA + k0 + a_col) * 2;
            ldsm4(ah, aa);
            ldsm4(al, oQl + aa);
#pragma unroll
            for (int nh = 0; nh < 2; nh++) {
                unsigned bh[2][4], bl[2][4];
#pragma unroll
                for (int kh = 0; kh < 2; kh++) {
                    uint32_t ba = sbase + (uint32_t)((b_row + nh * 32) * FSA + k0 + kh * 8) * 2;
                    ldsm4(bh[kh], oKh + ba);
                    ldsm4(bl[kh], oKl + ba);
                }
#pragma unroll
                for (int nt = 0; nt < 4; nt++) {
                    float* sc = s[nh * 4 + nt];
                    mma_bf16(sc, ah, bh[0][nt], bh[1][nt]);
                    mma_bf16(sc, ah, bl[0][nt], bl[1][nt]);
                    mma_bf16(sc, al, bh[0][nt], bh[1][nt]);
                }
            }
        }

        if (kt == qt) {
            int r0 = wrow + g, r1 = r0 + 8;
#pragma unroll
            for (int nt = 0; nt < 8; nt++) {
                int c0 = nt * 8 + 2 * t4, c1 = c0 + 1;
                if (c0 > r0) s[nt][0] = -1e30f;
                if (c1 > r0) s[nt][1] = -1e30f;
                if (c0 > r1) s[nt][2] = -1e30f;
                if (c1 > r1) s[nt][3] = -1e30f;
            }
        }

        float mx0 = -1e30f, mx1 = -1e30f;
#pragma unroll
        for (int nt = 0; nt < 8; nt++) {
            mx0 = fmaxf(mx0, fmaxf(s[nt][0], s[nt][1]));
            mx1 = fmaxf(mx1, fmaxf(s[nt][2], s[nt][3]));
        }
        mx0 = fmaxf(mx0, __shfl_xor_sync(0xffffffffu, mx0, 1));
        mx0 = fmaxf(mx0, __shfl_xor_sync(0xffffffffu, mx0, 2));
        mx1 = fmaxf(mx1, __shfl_xor_sync(0xffffffffu, mx1, 1));
        mx1 = fmaxf(mx1, __shfl_xor_sync(0xffffffffu, mx1, 2));

        float mn0 = fmaxf(m0, mx0), mn1 = fmaxf(m1, mx1);
        float alpha0 = __expf(m0 - mn0), alpha1 = __expf(m1 - mn1);
        m0 = mn0; m1 = mn1;

        float sum0 = 0.f, sum1 = 0.f;
#pragma unroll
        for (int nt = 0; nt < 8; nt++) {
            s[nt][0] = __expf(s[nt][0] - mn0);
            s[nt][1] = __expf(s[nt][1] - mn0);
            s[nt][2] = __expf(s[nt][2] - mn1);
            s[nt][3] = __expf(s[nt][3] - mn1);
            sum0 += s[nt][0] + s[nt][1];
            sum1 += s[nt][2] + s[nt][3];
        }
        sum0 += __shfl_xor_sync(0xffffffffu, sum0, 1);
        sum0 += __shfl_xor_sync(0xffffffffu, sum0, 2);
        sum1 += __shfl_xor_sync(0xffffffffu, sum1, 1);
        sum1 += __shfl_xor_sync(0xffffffffu, sum1, 2);
        l0 = l0 * alpha0 + sum0;
        l1 = l1 * alpha1 + sum1;

#pragma unroll
        for (int nt = 0; nt < 8; nt++) {
            o[nt][0] *= alpha0; o[nt][1] *= alpha0;
            o[nt][2] *= alpha1; o[nt][3] *= alpha1;
        }

#pragma unroll
        for (int ks = 0; ks < 4; ks++) {
            const int k0 = ks * 16;
            unsigned ah[4], al[4];
            {
                float* p0 = s[2 * ks];
                float* p1 = s[2 * ks + 1];
                splitp(p0[0], p0[1], ah[0], al[0]);
                splitp(p0[2], p0[3], ah[1], al[1]);
                splitp(p1[0], p1[1], ah[2], al[2]);
                splitp(p1[2], p1[3], ah[3], al[3]);
            }
#pragma unroll
            for (int nh = 0; nh < 4; nh++) {
                uint32_t va = sbase + (uint32_t)((k0 + v_row) * FSA + nh * 16 + v_col) * 2;
                unsigned vh[4], vl[4];
                ldsm4t(vh, oVh + va);
                ldsm4t(vl, oVl + va);
                float* o0 = o[nh * 2];
                float* o1 = o[nh * 2 + 1];
                mma_bf16(o0, ah, vh[0], vh[1]);
                mma_bf16(o0, ah, vl[0], vl[1]);
                mma_bf16(o0, al, vh[0], vh[1]);
                mma_bf16(o1, ah, vh[2], vh[3]);
                mma_bf16(o1, ah, vl[2], vl[3]);
                mma_bf16(o1, al, vh[2], vh[3]);
            }
        }
        __syncthreads();
    }

    // ---- epilogue: normalize, split to bf16 hi/lo ctx ----
    float inv0 = 1.f / l0, inv1 = 1.f / l1;
    int row0 = qt * 64 + wrow + g;
    size_t base0 = ((size_t)(b * TT + row0)) * HIDDEN + h * 64;
    size_t base1 = base0 + 8 * HIDDEN;
#pragma unroll
    for (int nt = 0; nt < 8; nt++) {
        int c = nt * 8 + 2 * t4;
        unsigned hp, lp;
        splitp(o[nt][0] * inv0, o[nt][1] * inv0, hp, lp);
        *(unsigned*)&ctx_h[base0 + c] = hp;
        *(unsigned*)&ctx_l[base0 + c] = lp;
        splitp(o[nt][2] * inv1, o[nt][3] * inv1, hp, lp);
        *(unsigned*)&ctx_h[base1 + c] = hp;
        *(unsigned*)&ctx_l[base1 + c] = lp;
    }
}

// ---------------------------------------------------------------------------
extern "C" void kernel_launch(void* const* d_in, const int* in_sizes, int n_in,
                              void* d_out, int out_size)
{
    const float* hs    = (const float*)d_in[0];
    const float* cos_t = (const float*)d_in[1];
    const float* sin_t = (const float*)d_in[2];
    const float* wqkv  = (const float*)d_in[3];
    const float* wo    = (const float*)d_in[4];
    float* out = (float*)d_out;

    float* qkv = nullptr;
    __nv_bfloat16 *hs_h, *hs_l, *wq_h, *wq_l, *wo_h, *wo_l, *ctx_h, *ctx_l;
    cudaGetSymbolAddress((void**)&qkv,  g_qkv);
    cudaGetSymbolAddress((void**)&hs_h, g_hs_h);
    cudaGetSymbolAddress((void**)&hs_l, g_hs_l);
    cudaGetSymbolAddress((void**)&wq_h, g_wq_h);
    cudaGetSymbolAddress((void**)&wq_l, g_wq_l);
    cudaGetSymbolAddress((void**)&wo_h, g_wo_h);
    cudaGetSymbolAddress((void**)&wo_l, g_wo_l);
    cudaGetSymbolAddress((void**)&ctx_h, g_ctx_h);
    cudaGetSymbolAddress((void**)&ctx_l, g_ctx_l);

    // 0) split inputs to bf16 hi/lo (one pass each)
    conv_split<<<(MROWS * HIDDEN / 4 + 255) / 256, 256>>>(hs, hs_h, hs_l, MROWS * HIDDEN / 4);
    conv_split<<<(QKV_O * HIDDEN / 4 + 255) / 256, 256>>>(wqkv, wq_h, wq_l, QKV_O * HIDDEN / 4);
    conv_split<<<(HIDDEN * HIDDEN / 4 + 255) / 256, 256>>>(wo, wo_h, wo_l, HIDDEN * HIDDEN / 4);

    const int gemm_smem = 2 * BUFB;  // 80 KB
    cudaFuncSetAttribute(gemm_bf16, cudaFuncAttributeMaxDynamicSharedMemorySize, gemm_smem);

    // 1) QKV = hs @ wqkv^T  [4096, 3072]
    gemm_bf16<<<dim3(QKV_O / 128, MROWS / 128), 256, gemm_smem>>>(
        hs_h, hs_l, wq_h, wq_l, qkv, MROWS, QKV_O, HIDDEN);

    // 2) RoPE
    rope_kernel<<<(BB * TT * 32 * 32) / 256, 256>>>(qkv, cos_t, sin_t);

    // 3) Flash attention (bf16x3 HMMA), writes ctx hi/lo
    const int fa_smem = 6 * FT * (int)sizeof(__nv_bfloat16);
    cudaFuncSetAttribute(flash_attn_mma, cudaFuncAttributeMaxDynamicSharedMemorySize, fa_smem);
    flash_attn_mma<<<dim3(TT / 64, NH, BB), 128, fa_smem>>>(qkv, ctx_h, ctx_l);

    // 4) out = ctx @ wo^T  [4096, 1024]
    gemm_bf16<<<dim3(HIDDEN / 128, MROWS / 128), 256, gemm_smem>>>(
        ctx_h, ctx_l, wo_h, wo_l, out, MROWS, HIDDEN, HIDDEN);
}

// round 8
// speedup vs baseline: 1.2676x; 1.2676x over previous
#include <cuda_runtime.h>
#include <cuda_bf16.h>
#include <cuda_fp16.h>
#include <cstdint>
#include <math.h>

#define BB 2
#define TT 2048
#define HIDDEN 1024
#define NH 16
#define QKV_O 3072   // (16 + 2*16) * 64
#define MROWS (BB*TT) // 4096

// Scratch (allocation-free rule: __device__ globals)
__device__ float g_qkv[(size_t)MROWS * QKV_O];            // [B*T, 3072] fp32
__device__ __half g_hs_f[(size_t)MROWS * HIDDEN];         // activations fp16
__device__ __half g_wq_h[(size_t)QKV_O * HIDDEN];
__device__ __half g_wq_l[(size_t)QKV_O * HIDDEN];
__device__ __half g_wo_h[(size_t)HIDDEN * HIDDEN];
__device__ __half g_wo_l[(size_t)HIDDEN * HIDDEN];
__device__ __half g_ctx[(size_t)MROWS * HIDDEN];          // attention out fp16

// ===========================================================================
// Helpers
// ===========================================================================
__device__ __forceinline__ uint32_t smem_to_u32(const void* p) {
    uint32_t a;
    asm("{ .reg .u64 t; cvta.to.shared.u64 t, %1; cvt.u32.u64 %0, t; }" : "=r"(a) : "l"(p));
    return a;
}
__device__ __forceinline__ void ldsm4(unsigned* r, uint32_t addr) {
    asm volatile("ldmatrix.sync.aligned.m8n8.x4.shared.b16 {%0,%1,%2,%3}, [%4];"
                 : "=r"(r[0]), "=r"(r[1]), "=r"(r[2]), "=r"(r[3]) : "r"(addr));
}
__device__ __forceinline__ void ldsm4t(unsigned* r, uint32_t addr) {
    asm volatile("ldmatrix.sync.aligned.m8n8.x4.trans.shared.b16 {%0,%1,%2,%3}, [%4];"
                 : "=r"(r[0]), "=r"(r[1]), "=r"(r[2]), "=r"(r[3]) : "r"(addr));
}
__device__ __forceinline__ void mma_bf16(float* c, const unsigned* a, unsigned b0, unsigned b1) {
    asm volatile("mma.sync.aligned.m16n8k16.row.col.f32.bf16.bf16.f32 "
                 "{%0,%1,%2,%3}, {%4,%5,%6,%7}, {%8,%9}, {%0,%1,%2,%3};"
                 : "+f"(c[0]), "+f"(c[1]), "+f"(c[2]), "+f"(c[3])
                 : "r"(a[0]), "r"(a[1]), "r"(a[2]), "r"(a[3]), "r"(b0), "r"(b1));
}
__device__ __forceinline__ void mma_f16(float* c, const unsigned* a, unsigned b0, unsigned b1) {
    asm volatile("mma.sync.aligned.m16n8k16.row.col.f32.f16.f16.f32 "
                 "{%0,%1,%2,%3}, {%4,%5,%6,%7}, {%8,%9}, {%0,%1,%2,%3};"
                 : "+f"(c[0]), "+f"(c[1]), "+f"(c[2]), "+f"(c[3])
                 : "r"(a[0]), "r"(a[1]), "r"(a[2]), "r"(a[3]), "r"(b0), "r"(b1));
}
__device__ __forceinline__ void split4(float4 v, uint2& hi, uint2& lo)   // bf16 (attention)
{
    __nv_bfloat16 h0 = __float2bfloat16_rn(v.x);
    __nv_bfloat16 h1 = __float2bfloat16_rn(v.y);
    __nv_bfloat16 h2 = __float2bfloat16_rn(v.z);
    __nv_bfloat16 h3 = __float2bfloat16_rn(v.w);
    __nv_bfloat16 l0 = __float2bfloat16_rn(v.x - __bfloat162float(h0));
    __nv_bfloat16 l1 = __float2bfloat16_rn(v.y - __bfloat162float(h1));
    __nv_bfloat16 l2 = __float2bfloat16_rn(v.z - __bfloat162float(h2));
    __nv_bfloat16 l3 = __float2bfloat16_rn(v.w - __bfloat162float(h3));
    __nv_bfloat162 hp0(h0, h1), hp1(h2, h3), lp0(l0, l1), lp1(l2, l3);
    hi.x = *(uint32_t*)&hp0; hi.y = *(uint32_t*)&hp1;
    lo.x = *(uint32_t*)&lp0; lo.y = *(uint32_t*)&lp1;
}
__device__ __forceinline__ void splitp(float x, float y, unsigned& h, unsigned& l) { // bf16
    __nv_bfloat16 hx = __float2bfloat16_rn(x), hy = __float2bfloat16_rn(y);
    __nv_bfloat16 lx = __float2bfloat16_rn(x - __bfloat162float(hx));
    __nv_bfloat16 ly = __float2bfloat16_rn(y - __bfloat162float(hy));
    __nv_bfloat162 hp(hx, hy), lp(lx, ly);
    h = *(unsigned*)&hp; l = *(unsigned*)&lp;
}
#define CP_ASYNC16(dst, src) \
    asm volatile("cp.async.cg.shared.global [%0], [%1], 16;" :: "r"(dst), "l"(src))
#define CP_COMMIT() asm volatile("cp.async.commit_group;" ::: "memory")
#define CP_WAIT0()  asm volatile("cp.async.wait_group 0;" ::: "memory")

// ===========================================================================
// Converters
// ===========================================================================
__global__ __launch_bounds__(256) void conv_f16(const float* __restrict__ x,
                                                __half* __restrict__ h, int n4)
{
    int i = blockIdx.x * blockDim.x + threadIdx.x;
    if (i >= n4) return;
    float4 v = ((const float4*)x)[i];
    __half2 p0 = __floats2half2_rn(v.x, v.y);
    __half2 p1 = __floats2half2_rn(v.z, v.w);
    uint2 o; o.x = *(uint32_t*)&p0; o.y = *(uint32_t*)&p1;
    ((uint2*)h)[i] = o;
}
__global__ __launch_bounds__(256) void conv_split_f16(const float* __restrict__ x,
                                                      __half* __restrict__ hi,
                                                      __half* __restrict__ lo, int n4)
{
    int i = blockIdx.x * blockDim.x + threadIdx.x;
    if (i >= n4) return;
    float4 v = ((const float4*)x)[i];
    __half h0 = __float2half_rn(v.x), h1 = __float2half_rn(v.y);
    __half h2 = __float2half_rn(v.z), h3 = __float2half_rn(v.w);
    __half l0 = __float2half_rn(v.x - __half2float(h0));
    __half l1 = __float2half_rn(v.y - __half2float(h1));
    __half l2 = __float2half_rn(v.z - __half2float(h2));
    __half l3 = __float2half_rn(v.w - __half2float(h3));
    __half2 hp0(h0, h1), hp1(h2, h3), lp0(l0, l1), lp1(l2, l3);
    uint2 oh, ol;
    oh.x = *(uint32_t*)&hp0; oh.y = *(uint32_t*)&hp1;
    ol.x = *(uint32_t*)&lp0; ol.y = *(uint32_t*)&lp1;
    ((uint2*)hi)[i] = oh;
    ((uint2*)lo)[i] = ol;
}

// ===========================================================================
// fp16x2 HMMA GEMM: C[M,N] = A[M,K] * (Bh+Bl)[N,K]^T
// A single fp16, B split hi/lo fp16. 128x128 tile, BK=32, 8 warps.
// 2 MMAs per (mt,nt,ks). cp.async double-buffered, 1 barrier/chunk.
// ===========================================================================
#define SA 40
#define TSB (128 * SA * 2)        // tile bytes (10240)
#define BUFB (3 * TSB)            // per-buffer: A, Bh, Bl (30720)

__global__ __launch_bounds__(256) void gemm_f16x2(const __half* __restrict__ A,
                                                  const __half* __restrict__ Bh,
                                                  const __half* __restrict__ Bl,
                                                  float* __restrict__ C,
                                                  int M, int N, int K)
{
    extern __shared__ char dsm[];
    const uint32_t sbase = smem_to_u32(dsm);

    const int tid  = threadIdx.x;
    const int wid  = tid >> 5;
    const int lane = tid & 31;
    const int warp_m = wid >> 2;
    const int warp_n = wid & 3;
    const int bm = blockIdx.y * 128;
    const int bn = blockIdx.x * 128;
    const int lj = lane & 7;
    const int li = lane >> 3;

    float c[4][4][4];
#pragma unroll
    for (int mt = 0; mt < 4; mt++)
#pragma unroll
        for (int nt = 0; nt < 4; nt++)
#pragma unroll
            for (int j = 0; j < 4; j++) c[mt][nt][j] = 0.f;

    const int a_row_base = warp_m * 64 + lj + ((li & 1) << 3);
    const int a_col_base = (li >> 1) << 3;
    const int b_row = warp_n * 32 + li * 8 + lj;

    // 3 tiles x 512 16B ops = 1536 ops / 256 threads = 6 per thread
    auto load_chunk = [&](int ch, int buf) {
#pragma unroll
        for (int i = 0; i < 6; i++) {
            const int tile = i >> 1;                  // 0=A 1=Bh 2=Bl
            const int v = ((i & 1) << 8) + tid;       // 0..511
            const int r = v >> 2;
            const int c8 = (v & 3) << 3;
            const __half* sp = (tile == 0) ? A : (tile == 1) ? Bh : Bl;
            const int grow = ((tile == 0) ? bm : bn) + r;
            uint32_t dst = sbase + buf * BUFB + tile * TSB + (uint32_t)(r * SA + c8) * 2;
            CP_ASYNC16(dst, sp + (size_t)grow * K + ch * 32 + c8);
        }
        CP_COMMIT();
    };

    const int nchunks = K >> 5;
    load_chunk(0, 0);

    for (int ch = 0; ch < nchunks; ch++) {
        const int buf = ch & 1;
        CP_WAIT0();
        __syncthreads();    // data ready AND all warps done with buf^1 compute
        if (ch + 1 < nchunks) load_chunk(ch + 1, buf ^ 1);

        const uint32_t base = sbase + buf * BUFB;
        const uint32_t oBh = TSB, oBl = 2 * TSB;
#pragma unroll
        for (int ks = 0; ks < 2; ks++) {
            const int k0 = ks * 16;
            unsigned bh[2][4], bl[2][4];
#pragma unroll
            for (int kh = 0; kh < 2; kh++) {
                uint32_t ba = base + (uint32_t)(b_row * SA + k0 + kh * 8) * 2;
                ldsm4(bh[kh], oBh + ba);
                ldsm4(bl[kh], oBl + ba);
            }
#pragma unroll
            for (int mt = 0; mt < 4; mt++) {
                unsigned a[4];
                uint32_t aa = base + (uint32_t)((a_row_base + mt * 16) * SA + k0 + a_col_base) * 2;
                ldsm4(a, aa);
#pragma unroll
                for (int nt = 0; nt < 4; nt++) {
                    mma_f16(c[mt][nt], a, bh[0][nt], bh[1][nt]);
                    mma_f16(c[mt][nt], a, bl[0][nt], bl[1][nt]);
                }
            }
        }
    }

    const int q  = lane >> 2;
    const int t4 = lane & 3;
#pragma unroll
    for (int mt = 0; mt < 4; mt++) {
        int row0 = bm + warp_m * 64 + mt * 16 + q;
#pragma unroll
        for (int nt = 0; nt < 4; nt++) {
            int col = bn + warp_n * 32 + nt * 8 + 2 * t4;
            *(float2*)&C[(size_t)row0 * N + col] =
                make_float2(c[mt][nt][0], c[mt][nt][1]);
            *(float2*)&C[(size_t)(row0 + 8) * N + col] =
                make_float2(c[mt][nt][2], c[mt][nt][3]);
        }
    }
}

// ---------------------------------------------------------------------------
// RoPE in-place on Q and K heads of qkv [B*T, 48, 64].
// ---------------------------------------------------------------------------
__global__ __launch_bounds__(256) void rope_kernel(float* __restrict__ qkv,
                                                   const float* __restrict__ cos_t,
                                                   const float* __restrict__ sin_t)
{
    int idx = blockIdx.x * blockDim.x + threadIdx.x;
    int half = idx & 31;
    int rest = idx >> 5;
    int head = rest & 31;
    int bt   = rest >> 5;
    int t    = bt & (TT - 1);
    float c = cos_t[t * 64 + half];
    float s = sin_t[t * 64 + half];
    size_t base = ((size_t)bt * 48 + head) * 64;
    float x1 = qkv[base + half];
    float x2 = qkv[base + 32 + half];
    qkv[base + half]      = x1 * c - x2 * s;
    qkv[base + 32 + half] = x2 * c + x1 * s;
}

// ===========================================================================
// bf16x3 HMMA flash attention (causal). Epilogue writes fp16 ctx.
// ===========================================================================
#define FSA 72
#define FT (64 * FSA)

__global__ __launch_bounds__(128) void flash_attn_mma(const float* __restrict__ qkv,
                                                      __half* __restrict__ ctx)
{
    extern __shared__ __nv_bfloat16 sh[];   // Qh Ql Kh Kl Vh Vl (54 KB)
    const uint32_t sbase = smem_to_u32(sh);
    const uint32_t oQl = FT * 2, oKh = FT * 4, oKl = FT * 6, oVh = FT * 8, oVl = FT * 10;

    const int qt = blockIdx.x;
    const int h  = blockIdx.y;
    const int b  = blockIdx.z;
    const int tid  = threadIdx.x;
    const int wid  = tid >> 5;
    const int lane = tid & 31;
    const int lj = lane & 7;
    const int li = lane >> 3;
    const int g  = lane >> 2;
    const int t4 = lane & 3;
    const int wrow = wid * 16;

#pragma unroll
    for (int i = 0; i < 8; i++) {
        int e = i * 128 + tid;
        int r = e >> 4;
        int c4 = (e & 15) << 2;
        float4 q4 = *(const float4*)&qkv[(((size_t)(b * TT + qt * 64 + r)) * 48 + h) * 64 + c4];
        q4.x *= 0.125f; q4.y *= 0.125f; q4.z *= 0.125f; q4.w *= 0.125f;
        uint2 hv, lv;
        split4(q4, hv, lv);
        uint32_t so = (uint32_t)(r * FSA + c4) * 2;
        *(uint2*)((char*)sh + so) = hv;
        *(uint2*)((char*)sh + oQl + so) = lv;
    }

    float m0 = -1e30f, m1 = -1e30f, l0 = 0.f, l1 = 0.f;
    float o[8][4];
#pragma unroll
    for (int nt = 0; nt < 8; nt++)
#pragma unroll
        for (int j = 0; j < 4; j++) o[nt][j] = 0.f;

    const int a_row = wrow + lj + ((li & 1) << 3);
    const int a_col = (li >> 1) << 3;
    const int b_row = li * 8 + lj;
    const int v_row = lj + ((li & 1) << 3);
    const int v_col = (lane >> 4) << 3;

    __syncthreads();

    for (int kt = 0; kt <= qt; kt++) {
#pragma unroll
        for (int i = 0; i < 8; i++) {
            int e = i * 128 + tid;
            int r = e >> 4;
            int c4 = (e & 15) << 2;
            size_t baseK = (((size_t)(b * TT + kt * 64 + r)) * 48 + NH + h) * 64 + c4;
            uint32_t so = (uint32_t)(r * FSA + c4) * 2;
            uint2 hv, lv;
            split4(*(const float4*)&qkv[baseK], hv, lv);
            *(uint2*)((char*)sh + oKh + so) = hv;
            *(uint2*)((char*)sh + oKl + so) = lv;
            split4(*(const float4*)&qkv[baseK + NH * 64], hv, lv);
            *(uint2*)((char*)sh + oVh + so) = hv;
            *(uint2*)((char*)sh + oVl + so) = lv;
        }
        __syncthreads();

        float s[8][4];
#pragma unroll
        for (int nt = 0; nt < 8; nt++)
#pragma unroll
            for (int j = 0; j < 4; j++) s[nt][j] = 0.f;

#pragma unroll
        for (int ks = 0; ks < 4; ks++) {
            const int k0 = ks * 16;
            unsigned ah[4], al[4];
            uint32_t aa = sbase + (uint32_t)(a_row * FSA + k0 + a_col) * 2;
            ldsm4(ah, aa);
            ldsm4(al, oQl + aa);
#pragma unroll
            for (int nh = 0; nh < 2; nh++) {
                unsigned bh[2][4], bl[2][4];
#pragma unroll
                for (int kh = 0; kh < 2; kh++) {
                    uint32_t ba = sbase + (uint32_t)((b_row + nh * 32) * FSA + k0 + kh * 8) * 2;
                    ldsm4(bh[kh], oKh + ba);
                    ldsm4(bl[kh], oKl + ba);
                }
#pragma unroll
                for (int nt = 0; nt < 4; nt++) {
                    float* sc = s[nh * 4 + nt];
                    mma_bf16(sc, ah, bh[0][nt], bh[1][nt]);
                    mma_bf16(sc, ah, bl[0][nt], bl[1][nt]);
                    mma_bf16(sc, al, bh[0][nt], bh[1][nt]);
                }
            }
        }

        if (kt == qt) {
            int r0 = wrow + g, r1 = r0 + 8;
#pragma unroll
            for (int nt = 0; nt < 8; nt++) {
                int c0 = nt * 8 + 2 * t4, c1 = c0 + 1;
                if (c0 > r0) s[nt][0] = -1e30f;
                if (c1 > r0) s[nt][1] = -1e30f;
                if (c0 > r1) s[nt][2] = -1e30f;
                if (c1 > r1) s[nt][3] = -1e30f;
            }
        }

        float mx0 = -1e30f, mx1 = -1e30f;
#pragma unroll
        for (int nt = 0; nt < 8; nt++) {
            mx0 = fmaxf(mx0, fmaxf(s[nt][0], s[nt][1]));
            mx1 = fmaxf(mx1, fmaxf(s[nt][2], s[nt][3]));
        }
        mx0 = fmaxf(mx0, __shfl_xor_sync(0xffffffffu, mx0, 1));
        mx0 = fmaxf(mx0, __shfl_xor_sync(0xffffffffu, mx0, 2));
        mx1 = fmaxf(mx1, __shfl_xor_sync(0xffffffffu, mx1, 1));
        mx1 = fmaxf(mx1, __shfl_xor_sync(0xffffffffu, mx1, 2));

        float mn0 = fmaxf(m0, mx0), mn1 = fmaxf(m1, mx1);
        float alpha0 = __expf(m0 - mn0), alpha1 = __expf(m1 - mn1);
        m0 = mn0; m1 = mn1;

        float sum0 = 0.f, sum1 = 0.f;
#pragma unroll
        for (int nt = 0; nt < 8; nt++) {
            s[nt][0] = __expf(s[nt][0] - mn0);
            s[nt][1] = __expf(s[nt][1] - mn0);
            s[nt][2] = __expf(s[nt][2] - mn1);
            s[nt][3] = __expf(s[nt][3] - mn1);
            sum0 += s[nt][0] + s[nt][1];
            sum1 += s[nt][2] + s[nt][3];
        }
        sum0 += __shfl_xor_sync(0xffffffffu, sum0, 1);
        sum0 += __shfl_xor_sync(0xffffffffu, sum0, 2);
        sum1 += __shfl_xor_sync(0xffffffffu, sum1, 1);
        sum1 += __shfl_xor_sync(0xffffffffu, sum1, 2);
        l0 = l0 * alpha0 + sum0;
        l1 = l1 * alpha1 + sum1;

#pragma unroll
        for (int nt = 0; nt < 8; nt++) {
            o[nt][0] *= alpha0; o[nt][1] *= alpha0;
            o[nt][2] *= alpha1; o[nt][3] *= alpha1;
        }

#pragma unroll
        for (int ks = 0; ks < 4; ks++) {
            const int k0 = ks * 16;
            unsigned ah[4], al[4];
            {
                float* p0 = s[2 * ks];
                float* p1 = s[2 * ks + 1];
                splitp(p0[0], p0[1], ah[0], al[0]);
                splitp(p0[2], p0[3], ah[1], al[1]);
                splitp(p1[0], p1[1], ah[2], al[2]);
                splitp(p1[2], p1[3], ah[3], al[3]);
            }
#pragma unroll
            for (int nh = 0; nh < 4; nh++) {
                uint32_t va = sbase + (uint32_t)((k0 + v_row) * FSA + nh * 16 + v_col) * 2;
                unsigned vh[4], vl[4];
                ldsm4t(vh, oVh + va);
                ldsm4t(vl, oVl + va);
                float* o0 = o[nh * 2];
                float* o1 = o[nh * 2 + 1];
                mma_bf16(o0, ah, vh[0], vh[1]);
                mma_bf16(o0, ah, vl[0], vl[1]);
                mma_bf16(o0, al, vh[0], vh[1]);
                mma_bf16(o1, ah, vh[2], vh[3]);
                mma_bf16(o1, ah, vl[2], vl[3]);
                mma_bf16(o1, al, vh[2], vh[3]);
            }
        }
        __syncthreads();
    }

    // ---- epilogue: normalize, write fp16 ctx ----
    float inv0 = 1.f / l0, inv1 = 1.f / l1;
    int row0 = qt * 64 + wrow + g;
    size_t base0 = ((size_t)(b * TT + row0)) * HIDDEN + h * 64;
    size_t base1 = base0 + 8 * HIDDEN;
#pragma unroll
    for (int nt = 0; nt < 8; nt++) {
        int c = nt * 8 + 2 * t4;
        __half2 p0 = __floats2half2_rn(o[nt][0] * inv0, o[nt][1] * inv0);
        __half2 p1 = __floats2half2_rn(o[nt][2] * inv1, o[nt][3] * inv1);
        *(unsigned*)&ctx[base0 + c] = *(unsigned*)&p0;
        *(unsigned*)&ctx[base1 + c] = *(unsigned*)&p1;
    }
}

// ---------------------------------------------------------------------------
extern "C" void kernel_launch(void* const* d_in, const int* in_sizes, int n_in,
                              void* d_out, int out_size)
{
    const float* hs    = (const float*)d_in[0];
    const float* cos_t = (const float*)d_in[1];
    const float* sin_t = (const float*)d_in[2];
    const float* wqkv  = (const float*)d_in[3];
    const float* wo    = (const float*)d_in[4];
    float* out = (float*)d_out;

    float* qkv = nullptr;
    __half *hs_f, *wq_h, *wq_l, *wo_h, *wo_l, *ctx;
    cudaGetSymbolAddress((void**)&qkv,  g_qkv);
    cudaGetSymbolAddress((void**)&hs_f, g_hs_f);
    cudaGetSymbolAddress((void**)&wq_h, g_wq_h);
    cudaGetSymbolAddress((void**)&wq_l, g_wq_l);
    cudaGetSymbolAddress((void**)&wo_h, g_wo_h);
    cudaGetSymbolAddress((void**)&wo_l, g_wo_l);
    cudaGetSymbolAddress((void**)&ctx,  g_ctx);

    // 0) converts
    conv_f16<<<MROWS * HIDDEN / 4 / 256, 256>>>(hs, hs_f, MROWS * HIDDEN / 4);
    conv_split_f16<<<QKV_O * HIDDEN / 4 / 256, 256>>>(wqkv, wq_h, wq_l, QKV_O * HIDDEN / 4);
    conv_split_f16<<<HIDDEN * HIDDEN / 4 / 256, 256>>>(wo, wo_h, wo_l, HIDDEN * HIDDEN / 4);

    const int gemm_smem = 2 * BUFB;  // 60 KB
    cudaFuncSetAttribute(gemm_f16x2, cudaFuncAttributeMaxDynamicSharedMemorySize, gemm_smem);

    // 1) QKV = hs @ wqkv^T
    gemm_f16x2<<<dim3(QKV_O / 128, MROWS / 128), 256, gemm_smem>>>(
        hs_f, wq_h, wq_l, qkv, MROWS, QKV_O, HIDDEN);

    // 2) RoPE
    rope_kernel<<<(BB * TT * 32 * 32) / 256, 256>>>(qkv, cos_t, sin_t);

    // 3) Flash attention (bf16x3 HMMA), writes fp16 ctx
    const int fa_smem = 6 * FT * (int)sizeof(__nv_bfloat16);
    cudaFuncSetAttribute(flash_attn_mma, cudaFuncAttributeMaxDynamicSharedMemorySize, fa_smem);
    flash_attn_mma<<<dim3(TT / 64, NH, BB), 128, fa_smem>>>(qkv, ctx);

    // 4) out = ctx @ wo^T
    gemm_f16x2<<<dim3(HIDDEN / 128, MROWS / 128), 256, gemm_smem>>>(
        ctx, wo_h, wo_l, out, MROWS, HIDDEN, HIDDEN);
}

// round 9
// speedup vs baseline: 1.4470x; 1.1415x over previous
#include <cuda_runtime.h>
#include <cuda_bf16.h>
#include <cuda_fp16.h>
#include <cstdint>
#include <math.h>

#define BB 2
#define TT 2048
#define HIDDEN 1024
#define NH 16
#define QKV_O 3072   // (16 + 2*16) * 64
#define MROWS (BB*TT) // 4096

// Scratch (allocation-free rule: __device__ globals)
__device__ float g_qkv[(size_t)MROWS * QKV_O];            // [B*T, 3072] fp32
__device__ __half g_hs_f[(size_t)MROWS * HIDDEN];
__device__ __half g_wq_h[(size_t)QKV_O * HIDDEN];
__device__ __half g_wq_l[(size_t)QKV_O * HIDDEN];
__device__ __half g_wo_h[(size_t)HIDDEN * HIDDEN];
__device__ __half g_wo_l[(size_t)HIDDEN * HIDDEN];
__device__ __half g_ctx[(size_t)MROWS * HIDDEN];
// head-major fp16 attention operands: [b, h, t, d] = ((b*NH+h)*TT + t)*64 + d
__device__ __half g_qh[(size_t)BB * NH * TT * 64];
__device__ __half g_ql[(size_t)BB * NH * TT * 64];
__device__ __half g_kf[(size_t)BB * NH * TT * 64];
__device__ __half g_vf[(size_t)BB * NH * TT * 64];

// ===========================================================================
// Helpers
// ===========================================================================
__device__ __forceinline__ uint32_t smem_to_u32(const void* p) {
    uint32_t a;
    asm("{ .reg .u64 t; cvta.to.shared.u64 t, %1; cvt.u32.u64 %0, t; }" : "=r"(a) : "l"(p));
    return a;
}
__device__ __forceinline__ void ldsm4(unsigned* r, uint32_t addr) {
    asm volatile("ldmatrix.sync.aligned.m8n8.x4.shared.b16 {%0,%1,%2,%3}, [%4];"
                 : "=r"(r[0]), "=r"(r[1]), "=r"(r[2]), "=r"(r[3]) : "r"(addr));
}
__device__ __forceinline__ void ldsm4t(unsigned* r, uint32_t addr) {
    asm volatile("ldmatrix.sync.aligned.m8n8.x4.trans.shared.b16 {%0,%1,%2,%3}, [%4];"
                 : "=r"(r[0]), "=r"(r[1]), "=r"(r[2]), "=r"(r[3]) : "r"(addr));
}
__device__ __forceinline__ void mma_f16(float* c, const unsigned* a, unsigned b0, unsigned b1) {
    asm volatile("mma.sync.aligned.m16n8k16.row.col.f32.f16.f16.f32 "
                 "{%0,%1,%2,%3}, {%4,%5,%6,%7}, {%8,%9}, {%0,%1,%2,%3};"
                 : "+f"(c[0]), "+f"(c[1]), "+f"(c[2]), "+f"(c[3])
                 : "r"(a[0]), "r"(a[1]), "r"(a[2]), "r"(a[3]), "r"(b0), "r"(b1));
}
__device__ __forceinline__ void splitpH(float x, float y, unsigned& h, unsigned& l) {
    __half hx = __float2half_rn(x), hy = __float2half_rn(y);
    __half lx = __float2half_rn(x - __half2float(hx));
    __half ly = __float2half_rn(y - __half2float(hy));
    __half2 hp(hx, hy), lp(lx, ly);
    h = *(unsigned*)&hp; l = *(unsigned*)&lp;
}
#define CP_ASYNC16(dst, src) \
    asm volatile("cp.async.cg.shared.global [%0], [%1], 16;" :: "r"(dst), "l"(src))
#define CP_COMMIT() asm volatile("cp.async.commit_group;" ::: "memory")
#define CP_WAIT0()  asm volatile("cp.async.wait_group 0;" ::: "memory")

// ===========================================================================
// Converters
// ===========================================================================
__global__ __launch_bounds__(256) void conv_f16(const float* __restrict__ x,
                                                __half* __restrict__ h, int n4)
{
    int i = blockIdx.x * blockDim.x + threadIdx.x;
    if (i >= n4) return;
    float4 v = ((const float4*)x)[i];
    __half2 p0 = __floats2half2_rn(v.x, v.y);
    __half2 p1 = __floats2half2_rn(v.z, v.w);
    uint2 o; o.x = *(uint32_t*)&p0; o.y = *(uint32_t*)&p1;
    ((uint2*)h)[i] = o;
}
__global__ __launch_bounds__(256) void conv_split_f16(const float* __restrict__ x,
                                                      __half* __restrict__ hi,
                                                      __half* __restrict__ lo, int n4)
{
    int i = blockIdx.x * blockDim.x + threadIdx.x;
    if (i >= n4) return;
    float4 v = ((const float4*)x)[i];
    __half h0 = __float2half_rn(v.x), h1 = __float2half_rn(v.y);
    __half h2 = __float2half_rn(v.z), h3 = __float2half_rn(v.w);
    __half l0 = __float2half_rn(v.x - __half2float(h0));
    __half l1 = __float2half_rn(v.y - __half2float(h1));
    __half l2 = __float2half_rn(v.z - __half2float(h2));
    __half l3 = __float2half_rn(v.w - __half2float(h3));
    __half2 hp0(h0, h1), hp1(h2, h3), lp0(l0, l1), lp1(l2, l3);
    uint2 oh, ol;
    oh.x = *(uint32_t*)&hp0; oh.y = *(uint32_t*)&hp1;
    ol.x = *(uint32_t*)&lp0; ol.y = *(uint32_t*)&lp1;
    ((uint2*)hi)[i] = oh;
    ((uint2*)lo)[i] = ol;
}

// ===========================================================================
// Fused RoPE + layout + fp16 convert:
// qkv fp32 [bt, 48, 64] -> Qh/Ql (RoPE, *0.125, hi/lo), Kf (RoPE), Vf
// all head-major [b, h, t, 64].
// ===========================================================================
__global__ __launch_bounds__(256) void rope_conv(const float* __restrict__ qkv,
                                                 const float* __restrict__ cos_t,
                                                 const float* __restrict__ sin_t,
                                                 __half* __restrict__ qh,
                                                 __half* __restrict__ ql,
                                                 __half* __restrict__ kf,
                                                 __half* __restrict__ vf)
{
    int idx = blockIdx.x * blockDim.x + threadIdx.x;  // bt*48*32
    int d5   = idx & 31;
    int rest = idx >> 5;
    int head = rest % 48;
    int bt   = rest / 48;
    int t = bt & (TT - 1);
    int b = bt >> 11;
    size_t src = ((size_t)bt * 48 + head) * 64;
    float x1 = qkv[src + d5];
    float x2 = qkv[src + 32 + d5];

    if (head < 32) {   // Q or K: RoPE
        float c = cos_t[t * 64 + d5];
        float s = sin_t[t * 64 + d5];
        float y1 = x1 * c - x2 * s;
        float y2 = x2 * c + x1 * s;
        if (head < NH) {     // Q: scale + hi/lo split
            y1 *= 0.125f; y2 *= 0.125f;
            size_t dst = (((size_t)(b * NH + head)) * TT + t) * 64;
            __half h1 = __float2half_rn(y1), h2 = __float2half_rn(y2);
            qh[dst + d5]      = h1;
            qh[dst + 32 + d5] = h2;
            ql[dst + d5]      = __float2half_rn(y1 - __half2float(h1));
            ql[dst + 32 + d5] = __float2half_rn(y2 - __half2float(h2));
        } else {             // K: single fp16
            size_t dst = (((size_t)(b * NH + head - NH)) * TT + t) * 64;
            kf[dst + d5]      = __float2half_rn(y1);
            kf[dst + 32 + d5] = __float2half_rn(y2);
        }
    } else {           // V: straight fp16
        size_t dst = (((size_t)(b * NH + head - 32)) * TT + t) * 64;
        vf[dst + d5]      = __float2half_rn(x1);
        vf[dst + 32 + d5] = __float2half_rn(x2);
    }
}

// ===========================================================================
// fp16x2 HMMA GEMM (round-8, proven): C = A * (Bh+Bl)^T
// ===========================================================================
#define SA 40
#define TSB (128 * SA * 2)
#define BUFB (3 * TSB)

__global__ __launch_bounds__(256) void gemm_f16x2(const __half* __restrict__ A,
                                                  const __half* __restrict__ Bh,
                                                  const __half* __restrict__ Bl,
                                                  float* __restrict__ C,
                                                  int M, int N, int K)
{
    extern __shared__ char dsm[];
    const uint32_t sbase = smem_to_u32(dsm);

    const int tid  = threadIdx.x;
    const int wid  = tid >> 5;
    const int lane = tid & 31;
    const int warp_m = wid >> 2;
    const int warp_n = wid & 3;
    const int bm = blockIdx.y * 128;
    const int bn = blockIdx.x * 128;
    const int lj = lane & 7;
    const int li = lane >> 3;

    float c[4][4][4];
#pragma unroll
    for (int mt = 0; mt < 4; mt++)
#pragma unroll
        for (int nt = 0; nt < 4; nt++)
#pragma unroll
            for (int j = 0; j < 4; j++) c[mt][nt][j] = 0.f;

    const int a_row_base = warp_m * 64 + lj + ((li & 1) << 3);
    const int a_col_base = (li >> 1) << 3;
    const int b_row = warp_n * 32 + li * 8 + lj;

    auto load_chunk = [&](int ch, int buf) {
#pragma unroll
        for (int i = 0; i < 6; i++) {
            const int tile = i >> 1;
            const int v = ((i & 1) << 8) + tid;
            const int r = v >> 2;
            const int c8 = (v & 3) << 3;
            const __half* sp = (tile == 0) ? A : (tile == 1) ? Bh : Bl;
            const int grow = ((tile == 0) ? bm : bn) + r;
            uint32_t dst = sbase + buf * BUFB + tile * TSB + (uint32_t)(r * SA + c8) * 2;
            CP_ASYNC16(dst, sp + (size_t)grow * K + ch * 32 + c8);
        }
        CP_COMMIT();
    };

    const int nchunks = K >> 5;
    load_chunk(0, 0);

    for (int ch = 0; ch < nchunks; ch++) {
        const int buf = ch & 1;
        CP_WAIT0();
        __syncthreads();
        if (ch + 1 < nchunks) load_chunk(ch + 1, buf ^ 1);

        const uint32_t base = sbase + buf * BUFB;
        const uint32_t oBh = TSB, oBl = 2 * TSB;
#pragma unroll
        for (int ks = 0; ks < 2; ks++) {
            const int k0 = ks * 16;
            unsigned bh[2][4], bl[2][4];
#pragma unroll
            for (int kh = 0; kh < 2; kh++) {
                uint32_t ba = base + (uint32_t)(b_row * SA + k0 + kh * 8) * 2;
                ldsm4(bh[kh], oBh + ba);
                ldsm4(bl[kh], oBl + ba);
            }
#pragma unroll
            for (int mt = 0; mt < 4; mt++) {
                unsigned a[4];
                uint32_t aa = base + (uint32_t)((a_row_base + mt * 16) * SA + k0 + a_col_base) * 2;
                ldsm4(a, aa);
#pragma unroll
                for (int nt = 0; nt < 4; nt++) {
                    mma_f16(c[mt][nt], a, bh[0][nt], bh[1][nt]);
                    mma_f16(c[mt][nt], a, bl[0][nt], bl[1][nt]);
                }
            }
        }
    }

    const int q  = lane >> 2;
    const int t4 = lane & 3;
#pragma unroll
    for (int mt = 0; mt < 4; mt++) {
        int row0 = bm + warp_m * 64 + mt * 16 + q;
#pragma unroll
        for (int nt = 0; nt < 4; nt++) {
            int col = bn + warp_n * 32 + nt * 8 + 2 * t4;
            *(float2*)&C[(size_t)row0 * N + col] =
                make_float2(c[mt][nt][0], c[mt][nt][1]);
            *(float2*)&C[(size_t)(row0 + 8) * N + col] =
                make_float2(c[mt][nt][2], c[mt][nt][3]);
        }
    }
}

// ===========================================================================
// fp16x2 HMMA flash attention (causal). Block = (64 q-rows, head, batch),
// 4 warps x 16 rows, Bc=64. Pre-converted fp16 inputs, S and PV 2 MMAs each.
// ===========================================================================
#define FSA 72
#define FT (64 * FSA)   // halves per tile

__global__ __launch_bounds__(128) void flash_attn_f16(const __half* __restrict__ Qh,
                                                      const __half* __restrict__ Ql,
                                                      const __half* __restrict__ Kf,
                                                      const __half* __restrict__ Vf,
                                                      __half* __restrict__ ctx)
{
    __shared__ __half sm_[4 * FT];      // Qh | Ql | K | V  (36 KB)
    const uint32_t sbase = smem_to_u32(sm_);
    const uint32_t oQl = FT * 2, oK = FT * 4, oV = FT * 6;   // byte offsets

    const int qt = blockIdx.x;
    const int h  = blockIdx.y;
    const int b  = blockIdx.z;
    const int tid  = threadIdx.x;
    const int wid  = tid >> 5;
    const int lane = tid & 31;
    const int lj = lane & 7;
    const int li = lane >> 3;
    const int g  = lane >> 2;
    const int t4 = lane & 3;
    const int wrow = wid * 16;

    const size_t headbase = ((size_t)(b * NH + h)) * TT * 64;

    // ---- Q tiles (hi+lo) via cp.async ----
#pragma unroll
    for (int i = 0; i < 8; i++) {
        int v = i * 128 + tid;          // 0..1023
        int tile = v >> 9;              // 0=Qh 1=Ql
        int r = (v >> 3) & 63;
        int c8 = (v & 7) << 3;
        const __half* sp = tile ? Ql : Qh;
        uint32_t dst = sbase + tile * (uint32_t)(FT * 2) + (uint32_t)(r * FSA + c8) * 2;
        CP_ASYNC16(dst, sp + headbase + (size_t)(qt * 64 + r) * 64 + c8);
    }
    CP_COMMIT();

    float m0 = -1e30f, m1 = -1e30f, l0 = 0.f, l1 = 0.f;
    float o[8][4];
#pragma unroll
    for (int nt = 0; nt < 8; nt++)
#pragma unroll
        for (int j = 0; j < 4; j++) o[nt][j] = 0.f;

    const int a_row = wrow + lj + ((li & 1) << 3);
    const int a_col = (li >> 1) << 3;
    const int b_row = li * 8 + lj;
    const int v_row = lj + ((li & 1) << 3);
    const int v_col = (lane >> 4) << 3;

    for (int kt = 0; kt <= qt; kt++) {
        // ---- K/V tiles via cp.async ----
#pragma unroll
        for (int i = 0; i < 8; i++) {
            int v = i * 128 + tid;
            int tile = v >> 9;          // 0=K 1=V
            int r = (v >> 3) & 63;
            int c8 = (v & 7) << 3;
            const __half* sp = tile ? Vf : Kf;
            uint32_t dst = sbase + oK + tile * (uint32_t)(FT * 2) + (uint32_t)(r * FSA + c8) * 2;
            CP_ASYNC16(dst, sp + headbase + (size_t)(kt * 64 + r) * 64 + c8);
        }
        CP_COMMIT();
        CP_WAIT0();
        __syncthreads();

        // ---- S = (Qh + Ql) @ K^T, fp16 x2 ----
        float s[8][4];
#pragma unroll
        for (int nt = 0; nt < 8; nt++)
#pragma unroll
            for (int j = 0; j < 4; j++) s[nt][j] = 0.f;

#pragma unroll
        for (int ks = 0; ks < 4; ks++) {
            const int k0 = ks * 16;
            unsigned ah[4], al[4];
            uint32_t aa = sbase + (uint32_t)(a_row * FSA + k0 + a_col) * 2;
            ldsm4(ah, aa);
            ldsm4(al, oQl + aa);
#pragma unroll
            for (int nh = 0; nh < 2; nh++) {
                unsigned kfr[2][4];
#pragma unroll
                for (int kh = 0; kh < 2; kh++) {
                    uint32_t ba = sbase + oK + (uint32_t)((b_row + nh * 32) * FSA + k0 + kh * 8) * 2;
                    ldsm4(kfr[kh], ba);
                }
#pragma unroll
                for (int nt = 0; nt < 4; nt++) {
                    float* sc = s[nh * 4 + nt];
                    mma_f16(sc, ah, kfr[0][nt], kfr[1][nt]);
                    mma_f16(sc, al, kfr[0][nt], kfr[1][nt]);
                }
            }
        }

        // ---- causal mask (diagonal tile) ----
        if (kt == qt) {
            int r0 = wrow + g, r1 = r0 + 8;
#pragma unroll
            for (int nt = 0; nt < 8; nt++) {
                int c0 = nt * 8 + 2 * t4, c1 = c0 + 1;
                if (c0 > r0) s[nt][0] = -1e30f;
                if (c1 > r0) s[nt][1] = -1e30f;
                if (c0 > r1) s[nt][2] = -1e30f;
                if (c1 > r1) s[nt][3] = -1e30f;
            }
        }

        // ---- online softmax ----
        float mx0 = -1e30f, mx1 = -1e30f;
#pragma unroll
        for (int nt = 0; nt < 8; nt++) {
            mx0 = fmaxf(mx0, fmaxf(s[nt][0], s[nt][1]));
            mx1 = fmaxf(mx1, fmaxf(s[nt][2], s[nt][3]));
        }
        mx0 = fmaxf(mx0, __shfl_xor_sync(0xffffffffu, mx0, 1));
        mx0 = fmaxf(mx0, __shfl_xor_sync(0xffffffffu, mx0, 2));
        mx1 = fmaxf(mx1, __shfl_xor_sync(0xffffffffu, mx1, 1));
        mx1 = fmaxf(mx1, __shfl_xor_sync(0xffffffffu, mx1, 2));

        float mn0 = fmaxf(m0, mx0), mn1 = fmaxf(m1, mx1);
        float alpha0 = __expf(m0 - mn0), alpha1 = __expf(m1 - mn1);
        m0 = mn0; m1 = mn1;

        float sum0 = 0.f, sum1 = 0.f;
#pragma unroll
        for (int nt = 0; nt < 8; nt++) {
            s[nt][0] = __expf(s[nt][0] - mn0);
            s[nt][1] = __expf(s[nt][1] - mn0);
            s[nt][2] = __expf(s[nt][2] - mn1);
            s[nt][3] = __expf(s[nt][3] - mn1);
            sum0 += s[nt][0] + s[nt][1];
            sum1 += s[nt][2] + s[nt][3];
        }
        sum0 += __shfl_xor_sync(0xffffffffu, sum0, 1);
        sum0 += __shfl_xor_sync(0xffffffffu, sum0, 2);
        sum1 += __shfl_xor_sync(0xffffffffu, sum1, 1);
        sum1 += __shfl_xor_sync(0xffffffffu, sum1, 2);
        l0 = l0 * alpha0 + sum0;
        l1 = l1 * alpha1 + sum1;

#pragma unroll
        for (int nt = 0; nt < 8; nt++) {
            o[nt][0] *= alpha0; o[nt][1] *= alpha0;
            o[nt][2] *= alpha1; o[nt][3] *= alpha1;
        }

        // ---- O += (Ph + Pl) @ V, fp16 x2 ----
#pragma unroll
        for (int ks = 0; ks < 4; ks++) {
            const int k0 = ks * 16;
            unsigned ah[4], al[4];
            {
                float* p0 = s[2 * ks];
                float* p1 = s[2 * ks + 1];
                splitpH(p0[0], p0[1], ah[0], al[0]);
                splitpH(p0[2], p0[3], ah[1], al[1]);
                splitpH(p1[0], p1[1], ah[2], al[2]);
                splitpH(p1[2], p1[3], ah[3], al[3]);
            }
#pragma unroll
            for (int nh = 0; nh < 4; nh++) {
                uint32_t va = sbase + oV + (uint32_t)((k0 + v_row) * FSA + nh * 16 + v_col) * 2;
                unsigned vfr[4];
                ldsm4t(vfr, va);
                float* o0 = o[nh * 2];
                float* o1 = o[nh * 2 + 1];
                mma_f16(o0, ah, vfr[0], vfr[1]);
                mma_f16(o0, al, vfr[0], vfr[1]);
                mma_f16(o1, ah, vfr[2], vfr[3]);
                mma_f16(o1, al, vfr[2], vfr[3]);
            }
        }
        __syncthreads();
    }

    // ---- epilogue: normalize, write fp16 ctx [B*T, H*D] ----
    float inv0 = 1.f / l0, inv1 = 1.f / l1;
    int row0 = qt * 64 + wrow + g;
    size_t base0 = ((size_t)(b * TT + row0)) * HIDDEN + h * 64;
    size_t base1 = base0 + 8 * HIDDEN;
#pragma unroll
    for (int nt = 0; nt < 8; nt++) {
        int c = nt * 8 + 2 * t4;
        __half2 p0 = __floats2half2_rn(o[nt][0] * inv0, o[nt][1] * inv0);
        __half2 p1 = __floats2half2_rn(o[nt][2] * inv1, o[nt][3] * inv1);
        *(unsigned*)&ctx[base0 + c] = *(unsigned*)&p0;
        *(unsigned*)&ctx[base1 + c] = *(unsigned*)&p1;
    }
}

// ---------------------------------------------------------------------------
extern "C" void kernel_launch(void* const* d_in, const int* in_sizes, int n_in,
                              void* d_out, int out_size)
{
    const float* hs    = (const float*)d_in[0];
    const float* cos_t = (const float*)d_in[1];
    const float* sin_t = (const float*)d_in[2];
    const float* wqkv  = (const float*)d_in[3];
    const float* wo    = (const float*)d_in[4];
    float* out = (float*)d_out;

    float* qkv = nullptr;
    __half *hs_f, *wq_h, *wq_l, *wo_h, *wo_l, *ctx, *qh, *ql, *kf, *vf;
    cudaGetSymbolAddress((void**)&qkv,  g_qkv);
    cudaGetSymbolAddress((void**)&hs_f, g_hs_f);
    cudaGetSymbolAddress((void**)&wq_h, g_wq_h);
    cudaGetSymbolAddress((void**)&wq_l, g_wq_l);
    cudaGetSymbolAddress((void**)&wo_h, g_wo_h);
    cudaGetSymbolAddress((void**)&wo_l, g_wo_l);
    cudaGetSymbolAddress((void**)&ctx,  g_ctx);
    cudaGetSymbolAddress((void**)&qh,   g_qh);
    cudaGetSymbolAddress((void**)&ql,   g_ql);
    cudaGetSymbolAddress((void**)&kf,   g_kf);
    cudaGetSymbolAddress((void**)&vf,   g_vf);

    // 0) converts
    conv_f16<<<MROWS * HIDDEN / 4 / 256, 256>>>(hs, hs_f, MROWS * HIDDEN / 4);
    conv_split_f16<<<QKV_O * HIDDEN / 4 / 256, 256>>>(wqkv, wq_h, wq_l, QKV_O * HIDDEN / 4);
    conv_split_f16<<<HIDDEN * HIDDEN / 4 / 256, 256>>>(wo, wo_h, wo_l, HIDDEN * HIDDEN / 4);

    const int gemm_smem = 2 * BUFB;  // 60 KB
    cudaFuncSetAttribute(gemm_f16x2, cudaFuncAttributeMaxDynamicSharedMemorySize, gemm_smem);

    // 1) QKV = hs @ wqkv^T
    gemm_f16x2<<<dim3(QKV_O / 128, MROWS / 128), 256, gemm_smem>>>(
        hs_f, wq_h, wq_l, qkv, MROWS, QKV_O, HIDDEN);

    // 2) Fused RoPE + fp16 head-major layout
    rope_conv<<<(MROWS * 48 * 32) / 256, 256>>>(qkv, cos_t, sin_t, qh, ql, kf, vf);

    // 3) Flash attention (fp16 x2 HMMA)
    flash_attn_f16<<<dim3(TT / 64, NH, BB), 128>>>(qh, ql, kf, vf, ctx);

    // 4) out = ctx @ wo^T
    gemm_f16x2<<<dim3(HIDDEN / 128, MROWS / 128), 256, gemm_smem>>>(
        ctx, wo_h, wo_l, out, MROWS, HIDDEN, HIDDEN);
}

// round 10
// speedup vs baseline: 1.7021x; 1.1763x over previous
#include <cuda_runtime.h>
#include <cuda_bf16.h>
#include <cuda_fp16.h>
#include <cstdint>
#include <math.h>

#define BB 2
#define TT 2048
#define HIDDEN 1024
#define NH 16
#define QKV_O 3072   // (16 + 2*16) * 64
#define MROWS (BB*TT) // 4096

// Scratch (allocation-free rule: __device__ globals)
__device__ float g_qkv[(size_t)MROWS * QKV_O];            // [B*T, 3072] fp32
__device__ __half g_hs_f[(size_t)MROWS * HIDDEN];
__device__ __half g_wq_h[(size_t)QKV_O * HIDDEN];
__device__ __half g_wq_l[(size_t)QKV_O * HIDDEN];
__device__ __half g_wo_h[(size_t)HIDDEN * HIDDEN];
__device__ __half g_ctx[(size_t)MROWS * HIDDEN];
// head-major fp16 attention operands: [b, h, t, d]
__device__ __half g_qh[(size_t)BB * NH * TT * 64];
__device__ __half g_ql[(size_t)BB * NH * TT * 64];
__device__ __half g_kf[(size_t)BB * NH * TT * 64];
__device__ __half g_vf[(size_t)BB * NH * TT * 64];

// ===========================================================================
// Helpers
// ===========================================================================
__device__ __forceinline__ uint32_t smem_to_u32(const void* p) {
    uint32_t a;
    asm("{ .reg .u64 t; cvta.to.shared.u64 t, %1; cvt.u32.u64 %0, t; }" : "=r"(a) : "l"(p));
    return a;
}
__device__ __forceinline__ void ldsm4(unsigned* r, uint32_t addr) {
    asm volatile("ldmatrix.sync.aligned.m8n8.x4.shared.b16 {%0,%1,%2,%3}, [%4];"
                 : "=r"(r[0]), "=r"(r[1]), "=r"(r[2]), "=r"(r[3]) : "r"(addr));
}
__device__ __forceinline__ void ldsm4t(unsigned* r, uint32_t addr) {
    asm volatile("ldmatrix.sync.aligned.m8n8.x4.trans.shared.b16 {%0,%1,%2,%3}, [%4];"
                 : "=r"(r[0]), "=r"(r[1]), "=r"(r[2]), "=r"(r[3]) : "r"(addr));
}
__device__ __forceinline__ void mma_f16(float* c, const unsigned* a, unsigned b0, unsigned b1) {
    asm volatile("mma.sync.aligned.m16n8k16.row.col.f32.f16.f16.f32 "
                 "{%0,%1,%2,%3}, {%4,%5,%6,%7}, {%8,%9}, {%0,%1,%2,%3};"
                 : "+f"(c[0]), "+f"(c[1]), "+f"(c[2]), "+f"(c[3])
                 : "r"(a[0]), "r"(a[1]), "r"(a[2]), "r"(a[3]), "r"(b0), "r"(b1));
}
__device__ __forceinline__ void splitpH(float x, float y, unsigned& h, unsigned& l) {
    __half hx = __float2half_rn(x), hy = __float2half_rn(y);
    __half lx = __float2half_rn(x - __half2float(hx));
    __half ly = __float2half_rn(y - __half2float(hy));
    __half2 hp(hx, hy), lp(lx, ly);
    h = *(unsigned*)&hp; l = *(unsigned*)&lp;
}
#define CP_ASYNC16(dst, src) \
    asm volatile("cp.async.cg.shared.global [%0], [%1], 16;" :: "r"(dst), "l"(src))
#define CP_COMMIT() asm volatile("cp.async.commit_group;" ::: "memory")
#define CP_WAIT0()  asm volatile("cp.async.wait_group 0;" ::: "memory")

// ===========================================================================
// Converters
// ===========================================================================
__global__ __launch_bounds__(256) void conv_f16(const float* __restrict__ x,
                                                __half* __restrict__ h, int n4)
{
    int i = blockIdx.x * blockDim.x + threadIdx.x;
    if (i >= n4) return;
    float4 v = ((const float4*)x)[i];
    __half2 p0 = __floats2half2_rn(v.x, v.y);
    __half2 p1 = __floats2half2_rn(v.z, v.w);
    uint2 o; o.x = *(uint32_t*)&p0; o.y = *(uint32_t*)&p1;
    ((uint2*)h)[i] = o;
}
__global__ __launch_bounds__(256) void conv_split_f16(const float* __restrict__ x,
                                                      __half* __restrict__ hi,
                                                      __half* __restrict__ lo, int n4)
{
    int i = blockIdx.x * blockDim.x + threadIdx.x;
    if (i >= n4) return;
    float4 v = ((const float4*)x)[i];
    __half h0 = __float2half_rn(v.x), h1 = __float2half_rn(v.y);
    __half h2 = __float2half_rn(v.z), h3 = __float2half_rn(v.w);
    __half l0 = __float2half_rn(v.x - __half2float(h0));
    __half l1 = __float2half_rn(v.y - __half2float(h1));
    __half l2 = __float2half_rn(v.z - __half2float(h2));
    __half l3 = __float2half_rn(v.w - __half2float(h3));
    __half2 hp0(h0, h1), hp1(h2, h3), lp0(l0, l1), lp1(l2, l3);
    uint2 oh, ol;
    oh.x = *(uint32_t*)&hp0; oh.y = *(uint32_t*)&hp1;
    ol.x = *(uint32_t*)&lp0; ol.y = *(uint32_t*)&lp1;
    ((uint2*)hi)[i] = oh;
    ((uint2*)lo)[i] = ol;
}

// ===========================================================================
// Fused RoPE + layout + fp16 convert (round-9, proven)
// ===========================================================================
__global__ __launch_bounds__(256) void rope_conv(const float* __restrict__ qkv,
                                                 const float* __restrict__ cos_t,
                                                 const float* __restrict__ sin_t,
                                                 __half* __restrict__ qh,
                                                 __half* __restrict__ ql,
                                                 __half* __restrict__ kf,
                                                 __half* __restrict__ vf)
{
    int idx = blockIdx.x * blockDim.x + threadIdx.x;  // bt*48*32
    int d5   = idx & 31;
    int rest = idx >> 5;
    int head = rest % 48;
    int bt   = rest / 48;
    int t = bt & (TT - 1);
    int b = bt >> 11;
    size_t src = ((size_t)bt * 48 + head) * 64;
    float x1 = qkv[src + d5];
    float x2 = qkv[src + 32 + d5];

    if (head < 32) {
        float c = cos_t[t * 64 + d5];
        float s = sin_t[t * 64 + d5];
        float y1 = x1 * c - x2 * s;
        float y2 = x2 * c + x1 * s;
        if (head < NH) {
            y1 *= 0.125f; y2 *= 0.125f;
            size_t dst = (((size_t)(b * NH + head)) * TT + t) * 64;
            __half h1 = __float2half_rn(y1), h2 = __float2half_rn(y2);
            qh[dst + d5]      = h1;
            qh[dst + 32 + d5] = h2;
            ql[dst + d5]      = __float2half_rn(y1 - __half2float(h1));
            ql[dst + 32 + d5] = __float2half_rn(y2 - __half2float(h2));
        } else {
            size_t dst = (((size_t)(b * NH + head - NH)) * TT + t) * 64;
            kf[dst + d5]      = __float2half_rn(y1);
            kf[dst + 32 + d5] = __float2half_rn(y2);
        }
    } else {
        size_t dst = (((size_t)(b * NH + head - 32)) * TT + t) * 64;
        vf[dst + d5]      = __float2half_rn(x1);
        vf[dst + 32 + d5] = __float2half_rn(x2);
    }
}

// ===========================================================================
// fp16 HMMA GEMMs: C[.., ldc] = A[M,K] * B[N,K]^T
// x2: B split hi/lo (2 MMAs).  x1: B single (1 MMA).
// 128x128 tile, BK=32, 8 warps, cp.async double-buffered.
// ===========================================================================
#define SA 40
#define TSB (128 * SA * 2)
#define BUFB2 (3 * TSB)       // x2: A, Bh, Bl
#define BUFB1 (2 * TSB)       // x1: A, B

__global__ __launch_bounds__(256) void gemm_f16x2(const __half* __restrict__ A,
                                                  const __half* __restrict__ Bh,
                                                  const __half* __restrict__ Bl,
                                                  float* __restrict__ C,
                                                  int ldc, int K)
{
    extern __shared__ char dsm[];
    const uint32_t sbase = smem_to_u32(dsm);

    const int tid  = threadIdx.x;
    const int wid  = tid >> 5;
    const int lane = tid & 31;
    const int warp_m = wid >> 2;
    const int warp_n = wid & 3;
    const int bm = blockIdx.y * 128;
    const int bn = blockIdx.x * 128;
    const int lj = lane & 7;
    const int li = lane >> 3;

    float c[4][4][4];
#pragma unroll
    for (int mt = 0; mt < 4; mt++)
#pragma unroll
        for (int nt = 0; nt < 4; nt++)
#pragma unroll
            for (int j = 0; j < 4; j++) c[mt][nt][j] = 0.f;

    const int a_row_base = warp_m * 64 + lj + ((li & 1) << 3);
    const int a_col_base = (li >> 1) << 3;
    const int b_row = warp_n * 32 + li * 8 + lj;

    auto load_chunk = [&](int ch, int buf) {
#pragma unroll
        for (int i = 0; i < 6; i++) {
            const int tile = i >> 1;
            const int v = ((i & 1) << 8) + tid;
            const int r = v >> 2;
            const int c8 = (v & 3) << 3;
            const __half* sp = (tile == 0) ? A : (tile == 1) ? Bh : Bl;
            const int grow = ((tile == 0) ? bm : bn) + r;
            uint32_t dst = sbase + buf * BUFB2 + tile * TSB + (uint32_t)(r * SA + c8) * 2;
            CP_ASYNC16(dst, sp + (size_t)grow * K + ch * 32 + c8);
        }
        CP_COMMIT();
    };

    const int nchunks = K >> 5;
    load_chunk(0, 0);

    for (int ch = 0; ch < nchunks; ch++) {
        const int buf = ch & 1;
        CP_WAIT0();
        __syncthreads();
        if (ch + 1 < nchunks) load_chunk(ch + 1, buf ^ 1);

        const uint32_t base = sbase + buf * BUFB2;
        const uint32_t oBh = TSB, oBl = 2 * TSB;
#pragma unroll
        for (int ks = 0; ks < 2; ks++) {
            const int k0 = ks * 16;
            unsigned bh[2][4], bl[2][4];
#pragma unroll
            for (int kh = 0; kh < 2; kh++) {
                uint32_t ba = base + (uint32_t)(b_row * SA + k0 + kh * 8) * 2;
                ldsm4(bh[kh], oBh + ba);
                ldsm4(bl[kh], oBl + ba);
            }
#pragma unroll
            for (int mt = 0; mt < 4; mt++) {
                unsigned a[4];
                uint32_t aa = base + (uint32_t)((a_row_base + mt * 16) * SA + k0 + a_col_base) * 2;
                ldsm4(a, aa);
#pragma unroll
                for (int nt = 0; nt < 4; nt++) {
                    mma_f16(c[mt][nt], a, bh[0][nt], bh[1][nt]);
                    mma_f16(c[mt][nt], a, bl[0][nt], bl[1][nt]);
                }
            }
        }
    }

    const int q  = lane >> 2;
    const int t4 = lane & 3;
#pragma unroll
    for (int mt = 0; mt < 4; mt++) {
        int row0 = bm + warp_m * 64 + mt * 16 + q;
#pragma unroll
        for (int nt = 0; nt < 4; nt++) {
            int col = bn + warp_n * 32 + nt * 8 + 2 * t4;
            *(float2*)&C[(size_t)row0 * ldc + col] =
                make_float2(c[mt][nt][0], c[mt][nt][1]);
            *(float2*)&C[(size_t)(row0 + 8) * ldc + col] =
                make_float2(c[mt][nt][2], c[mt][nt][3]);
        }
    }
}

__global__ __launch_bounds__(256) void gemm_f16x1(const __half* __restrict__ A,
                                                  const __half* __restrict__ Bm,
                                                  float* __restrict__ C,
                                                  int ldc, int K)
{
    extern __shared__ char dsm[];
    const uint32_t sbase = smem_to_u32(dsm);

    const int tid  = threadIdx.x;
    const int wid  = tid >> 5;
    const int lane = tid & 31;
    const int warp_m = wid >> 2;
    const int warp_n = wid & 3;
    const int bm = blockIdx.y * 128;
    const int bn = blockIdx.x * 128;
    const int lj = lane & 7;
    const int li = lane >> 3;

    float c[4][4][4];
#pragma unroll
    for (int mt = 0; mt < 4; mt++)
#pragma unroll
        for (int nt = 0; nt < 4; nt++)
#pragma unroll
            for (int j = 0; j < 4; j++) c[mt][nt][j] = 0.f;

    const int a_row_base = warp_m * 64 + lj + ((li & 1) << 3);
    const int a_col_base = (li >> 1) << 3;
    const int b_row = warp_n * 32 + li * 8 + lj;

    auto load_chunk = [&](int ch, int buf) {
#pragma unroll
        for (int i = 0; i < 4; i++) {
            const int tile = i >> 1;                 // 0=A 1=B
            const int v = ((i & 1) << 8) + tid;
            const int r = v >> 2;
            const int c8 = (v & 3) << 3;
            const __half* sp = (tile == 0) ? A : Bm;
            const int grow = ((tile == 0) ? bm : bn) + r;
            uint32_t dst = sbase + buf * BUFB1 + tile * TSB + (uint32_t)(r * SA + c8) * 2;
            CP_ASYNC16(dst, sp + (size_t)grow * K + ch * 32 + c8);
        }
        CP_COMMIT();
    };

    const int nchunks = K >> 5;
    load_chunk(0, 0);

    for (int ch = 0; ch < nchunks; ch++) {
        const int buf = ch & 1;
        CP_WAIT0();
        __syncthreads();
        if (ch + 1 < nchunks) load_chunk(ch + 1, buf ^ 1);

        const uint32_t base = sbase + buf * BUFB1;
        const uint32_t oB = TSB;
#pragma unroll
        for (int ks = 0; ks < 2; ks++) {
            const int k0 = ks * 16;
            unsigned bh[2][4];
#pragma unroll
            for (int kh = 0; kh < 2; kh++) {
                uint32_t ba = base + (uint32_t)(b_row * SA + k0 + kh * 8) * 2;
                ldsm4(bh[kh], oB + ba);
            }
#pragma unroll
            for (int mt = 0; mt < 4; mt++) {
                unsigned a[4];
                uint32_t aa = base + (uint32_t)((a_row_base + mt * 16) * SA + k0 + a_col_base) * 2;
                ldsm4(a, aa);
#pragma unroll
                for (int nt = 0; nt < 4; nt++)
                    mma_f16(c[mt][nt], a, bh[0][nt], bh[1][nt]);
            }
        }
    }

    const int q  = lane >> 2;
    const int t4 = lane & 3;
#pragma unroll
    for (int mt = 0; mt < 4; mt++) {
        int row0 = bm + warp_m * 64 + mt * 16 + q;
#pragma unroll
        for (int nt = 0; nt < 4; nt++) {
            int col = bn + warp_n * 32 + nt * 8 + 2 * t4;
            *(float2*)&C[(size_t)row0 * ldc + col] =
                make_float2(c[mt][nt][0], c[mt][nt][1]);
            *(float2*)&C[(size_t)(row0 + 8) * ldc + col] =
                make_float2(c[mt][nt][2], c[mt][nt][3]);
        }
    }
}

// ===========================================================================
// fp16x2 HMMA flash attention (round-9, proven)
// ===========================================================================
#define FSA 72
#define FT (64 * FSA)

__global__ __launch_bounds__(128) void flash_attn_f16(const __half* __restrict__ Qh,
                                                      const __half* __restrict__ Ql,
                                                      const __half* __restrict__ Kf,
                                                      const __half* __restrict__ Vf,
                                                      __half* __restrict__ ctx)
{
    __shared__ __half sm_[4 * FT];      // Qh | Ql | K | V (36 KB)
    const uint32_t sbase = smem_to_u32(sm_);
    const uint32_t oQl = FT * 2, oK = FT * 4, oV = FT * 6;

    const int qt = blockIdx.x;
    const int h  = blockIdx.y;
    const int b  = blockIdx.z;
    const int tid  = threadIdx.x;
    const int wid  = tid >> 5;
    const int lane = tid & 31;
    const int lj = lane & 7;
    const int li = lane >> 3;
    const int g  = lane >> 2;
    const int t4 = lane & 3;
    const int wrow = wid * 16;

    const size_t headbase = ((size_t)(b * NH + h)) * TT * 64;

#pragma unroll
    for (int i = 0; i < 8; i++) {
        int v = i * 128 + tid;
        int tile = v >> 9;
        int r = (v >> 3) & 63;
        int c8 = (v & 7) << 3;
        const __half* sp = tile ? Ql : Qh;
        uint32_t dst = sbase + tile * (uint32_t)(FT * 2) + (uint32_t)(r * FSA + c8) * 2;
        CP_ASYNC16(dst, sp + headbase + (size_t)(qt * 64 + r) * 64 + c8);
    }
    CP_COMMIT();

    float m0 = -1e30f, m1 = -1e30f, l0 = 0.f, l1 = 0.f;
    float o[8][4];
#pragma unroll
    for (int nt = 0; nt < 8; nt++)
#pragma unroll
        for (int j = 0; j < 4; j++) o[nt][j] = 0.f;

    const int a_row = wrow + lj + ((li & 1) << 3);
    const int a_col = (li >> 1) << 3;
    const int b_row = li * 8 + lj;
    const int v_row = lj + ((li & 1) << 3);
    const int v_col = (lane >> 4) << 3;

    for (int kt = 0; kt <= qt; kt++) {
#pragma unroll
        for (int i = 0; i < 8; i++) {
            int v = i * 128 + tid;
            int tile = v >> 9;
            int r = (v >> 3) & 63;
            int c8 = (v & 7) << 3;
            const __half* sp = tile ? Vf : Kf;
            uint32_t dst = sbase + oK + tile * (uint32_t)(FT * 2) + (uint32_t)(r * FSA + c8) * 2;
            CP_ASYNC16(dst, sp + headbase + (size_t)(kt * 64 + r) * 64 + c8);
        }
        CP_COMMIT();
        CP_WAIT0();
        __syncthreads();

        float s[8][4];
#pragma unroll
        for (int nt = 0; nt < 8; nt++)
#pragma unroll
            for (int j = 0; j < 4; j++) s[nt][j] = 0.f;

#pragma unroll
        for (int ks = 0; ks < 4; ks++) {
            const int k0 = ks * 16;
            unsigned ah[4], al[4];
            uint32_t aa = sbase + (uint32_t)(a_row * FSA + k0 + a_col) * 2;
            ldsm4(ah, aa);
            ldsm4(al, oQl + aa);
#pragma unroll
            for (int nh = 0; nh < 2; nh++) {
                unsigned kfr[2][4];
#pragma unroll
                for (int kh = 0; kh < 2; kh++) {
                    uint32_t ba = sbase + oK + (uint32_t)((b_row + nh * 32) * FSA + k0 + kh * 8) * 2;
                    ldsm4(kfr[kh], ba);
                }
#pragma unroll
                for (int nt = 0; nt < 4; nt++) {
                    float* sc = s[nh * 4 + nt];
                    mma_f16(sc, ah, kfr[0][nt], kfr[1][nt]);
                    mma_f16(sc, al, kfr[0][nt], kfr[1][nt]);
                }
            }
        }

        if (kt == qt) {
            int r0 = wrow + g, r1 = r0 + 8;
#pragma unroll
            for (int nt = 0; nt < 8; nt++) {
                int c0 = nt * 8 + 2 * t4, c1 = c0 + 1;
                if (c0 > r0) s[nt][0] = -1e30f;
                if (c1 > r0) s[nt][1] = -1e30f;
                if (c0 > r1) s[nt][2] = -1e30f;
                if (c1 > r1) s[nt][3] = -1e30f;
            }
        }

        float mx0 = -1e30f, mx1 = -1e30f;
#pragma unroll
        for (int nt = 0; nt < 8; nt++) {
            mx0 = fmaxf(mx0, fmaxf(s[nt][0], s[nt][1]));
            mx1 = fmaxf(mx1, fmaxf(s[nt][2], s[nt][3]));
        }
        mx0 = fmaxf(mx0, __shfl_xor_sync(0xffffffffu, mx0, 1));
        mx0 = fmaxf(mx0, __shfl_xor_sync(0xffffffffu, mx0, 2));
        mx1 = fmaxf(mx1, __shfl_xor_sync(0xffffffffu, mx1, 1));
        mx1 = fmaxf(mx1, __shfl_xor_sync(0xffffffffu, mx1, 2));

        float mn0 = fmaxf(m0, mx0), mn1 = fmaxf(m1, mx1);
        float alpha0 = __expf(m0 - mn0), alpha1 = __expf(m1 - mn1);
        m0 = mn0; m1 = mn1;

        float sum0 = 0.f, sum1 = 0.f;
#pragma unroll
        for (int nt = 0; nt < 8; nt++) {
            s[nt][0] = __expf(s[nt][0] - mn0);
            s[nt][1] = __expf(s[nt][1] - mn0);
            s[nt][2] = __expf(s[nt][2] - mn1);
            s[nt][3] = __expf(s[nt][3] - mn1);
            sum0 += s[nt][0] + s[nt][1];
            sum1 += s[nt][2] + s[nt][3];
        }
        sum0 += __shfl_xor_sync(0xffffffffu, sum0, 1);
        sum0 += __shfl_xor_sync(0xffffffffu, sum0, 2);
        sum1 += __shfl_xor_sync(0xffffffffu, sum1, 1);
        sum1 += __shfl_xor_sync(0xffffffffu, sum1, 2);
        l0 = l0 * alpha0 + sum0;
        l1 = l1 * alpha1 + sum1;

#pragma unroll
        for (int nt = 0; nt < 8; nt++) {
            o[nt][0] *= alpha0; o[nt][1] *= alpha0;
            o[nt][2] *= alpha1; o[nt][3] *= alpha1;
        }

#pragma unroll
        for (int ks = 0; ks < 4; ks++) {
            const int k0 = ks * 16;
            unsigned ah[4], al[4];
            {
                float* p0 = s[2 * ks];
                float* p1 = s[2 * ks + 1];
                splitpH(p0[0], p0[1], ah[0], al[0]);
                splitpH(p0[2], p0[3], ah[1], al[1]);
                splitpH(p1[0], p1[1], ah[2], al[2]);
                splitpH(p1[2], p1[3], ah[3], al[3]);
            }
#pragma unroll
            for (int nh = 0; nh < 4; nh++) {
                uint32_t va = sbase + oV + (uint32_t)((k0 + v_row) * FSA + nh * 16 + v_col) * 2;
                unsigned vfr[4];
                ldsm4t(vfr, va);
                float* o0 = o[nh * 2];
                float* o1 = o[nh * 2 + 1];
                mma_f16(o0, ah, vfr[0], vfr[1]);
                mma_f16(o0, al, vfr[0], vfr[1]);
                mma_f16(o1, ah, vfr[2], vfr[3]);
                mma_f16(o1, al, vfr[2], vfr[3]);
            }
        }
        __syncthreads();
    }

    float inv0 = 1.f / l0, inv1 = 1.f / l1;
    int row0 = qt * 64 + wrow + g;
    size_t base0 = ((size_t)(b * TT + row0)) * HIDDEN + h * 64;
    size_t base1 = base0 + 8 * HIDDEN;
#pragma unroll
    for (int nt = 0; nt < 8; nt++) {
        int c = nt * 8 + 2 * t4;
        __half2 p0 = __floats2half2_rn(o[nt][0] * inv0, o[nt][1] * inv0);
        __half2 p1 = __floats2half2_rn(o[nt][2] * inv1, o[nt][3] * inv1);
        *(unsigned*)&ctx[base0 + c] = *(unsigned*)&p0;
        *(unsigned*)&ctx[base1 + c] = *(unsigned*)&p1;
    }
}

// ---------------------------------------------------------------------------
extern "C" void kernel_launch(void* const* d_in, const int* in_sizes, int n_in,
                              void* d_out, int out_size)
{
    const float* hs    = (const float*)d_in[0];
    const float* cos_t = (const float*)d_in[1];
    const float* sin_t = (const float*)d_in[2];
    const float* wqkv  = (const float*)d_in[3];
    const float* wo    = (const float*)d_in[4];
    float* out = (float*)d_out;

    float* qkv = nullptr;
    __half *hs_f, *wq_h, *wq_l, *wo_h, *ctx, *qh, *ql, *kf, *vf;
    cudaGetSymbolAddress((void**)&qkv,  g_qkv);
    cudaGetSymbolAddress((void**)&hs_f, g_hs_f);
    cudaGetSymbolAddress((void**)&wq_h, g_wq_h);
    cudaGetSymbolAddress((void**)&wq_l, g_wq_l);
    cudaGetSymbolAddress((void**)&wo_h, g_wo_h);
    cudaGetSymbolAddress((void**)&ctx,  g_ctx);
    cudaGetSymbolAddress((void**)&qh,   g_qh);
    cudaGetSymbolAddress((void**)&ql,   g_ql);
    cudaGetSymbolAddress((void**)&kf,   g_kf);
    cudaGetSymbolAddress((void**)&vf,   g_vf);

    // 0) converts
    conv_f16<<<MROWS * HIDDEN / 4 / 256, 256>>>(hs, hs_f, MROWS * HIDDEN / 4);
    conv_split_f16<<<QKV_O * HIDDEN / 4 / 256, 256>>>(wqkv, wq_h, wq_l, QKV_O * HIDDEN / 4);
    conv_f16<<<HIDDEN * HIDDEN / 4 / 256, 256>>>(wo, wo_h, HIDDEN * HIDDEN / 4);

    cudaFuncSetAttribute(gemm_f16x2, cudaFuncAttributeMaxDynamicSharedMemorySize, 2 * BUFB2);
    cudaFuncSetAttribute(gemm_f16x1, cudaFuncAttributeMaxDynamicSharedMemorySize, 2 * BUFB1);

    // 1a) Q columns of QKV (x2 weights, N=1024)
    gemm_f16x2<<<dim3(8, MROWS / 128), 256, 2 * BUFB2>>>(
        hs_f, wq_h, wq_l, qkv, QKV_O, HIDDEN);
    // 1b) K,V columns of QKV (x1 weights, N=2048)
    gemm_f16x1<<<dim3(16, MROWS / 128), 256, 2 * BUFB1>>>(
        hs_f, wq_h + (size_t)HIDDEN * HIDDEN, qkv + HIDDEN, QKV_O, HIDDEN);

    // 2) Fused RoPE + fp16 head-major layout
    rope_conv<<<(MROWS * 48 * 32) / 256, 256>>>(qkv, cos_t, sin_t, qh, ql, kf, vf);

    // 3) Flash attention (fp16 x2 HMMA)
    flash_attn_f16<<<dim3(TT / 64, NH, BB), 128>>>(qh, ql, kf, vf, ctx);

    // 4) out = ctx @ wo^T (x1 weights)
    gemm_f16x1<<<dim3(8, MROWS / 128), 256, 2 * BUFB1>>>(
        ctx, wo_h, out, HIDDEN, HIDDEN);
}

// round 11
// speedup vs baseline: 1.9697x; 1.1572x over previous
#include <cuda_runtime.h>
#include <cuda_bf16.h>
#include <cuda_fp16.h>
#include <cstdint>
#include <math.h>

#define BB 2
#define TT 2048
#define HIDDEN 1024
#define NH 16
#define QKV_O 3072   // (16 + 2*16) * 64
#define MROWS (BB*TT) // 4096

// Scratch (allocation-free rule: __device__ globals)
__device__ float g_qkv[(size_t)MROWS * QKV_O];            // [B*T, 3072] fp32
__device__ __half g_hs_f[(size_t)MROWS * HIDDEN];
__device__ __half g_wq_h[(size_t)QKV_O * HIDDEN];
__device__ __half g_wq_l[(size_t)QKV_O * HIDDEN];
__device__ __half g_wo_h[(size_t)HIDDEN * HIDDEN];
__device__ __half g_ctx[(size_t)MROWS * HIDDEN];
// head-major fp16 attention operands: [b, h, t, d]
__device__ __half g_qf[(size_t)BB * NH * TT * 64];
__device__ __half g_kf[(size_t)BB * NH * TT * 64];
__device__ __half g_vf[(size_t)BB * NH * TT * 64];

// ===========================================================================
// Helpers
// ===========================================================================
__device__ __forceinline__ uint32_t smem_to_u32(const void* p) {
    uint32_t a;
    asm("{ .reg .u64 t; cvta.to.shared.u64 t, %1; cvt.u32.u64 %0, t; }" : "=r"(a) : "l"(p));
    return a;
}
__device__ __forceinline__ void ldsm4(unsigned* r, uint32_t addr) {
    asm volatile("ldmatrix.sync.aligned.m8n8.x4.shared.b16 {%0,%1,%2,%3}, [%4];"
                 : "=r"(r[0]), "=r"(r[1]), "=r"(r[2]), "=r"(r[3]) : "r"(addr));
}
__device__ __forceinline__ void ldsm4t(unsigned* r, uint32_t addr) {
    asm volatile("ldmatrix.sync.aligned.m8n8.x4.trans.shared.b16 {%0,%1,%2,%3}, [%4];"
                 : "=r"(r[0]), "=r"(r[1]), "=r"(r[2]), "=r"(r[3]) : "r"(addr));
}
__device__ __forceinline__ void mma_f16(float* c, const unsigned* a, unsigned b0, unsigned b1) {
    asm volatile("mma.sync.aligned.m16n8k16.row.col.f32.f16.f16.f32 "
                 "{%0,%1,%2,%3}, {%4,%5,%6,%7}, {%8,%9}, {%0,%1,%2,%3};"
                 : "+f"(c[0]), "+f"(c[1]), "+f"(c[2]), "+f"(c[3])
                 : "r"(a[0]), "r"(a[1]), "r"(a[2]), "r"(a[3]), "r"(b0), "r"(b1));
}
__device__ __forceinline__ unsigned pkH(float x, float y) {
    __half2 p(__float2half_rn(x), __float2half_rn(y));
    return *(unsigned*)&p;
}
#define CP_ASYNC16(dst, src) \
    asm volatile("cp.async.cg.shared.global [%0], [%1], 16;" :: "r"(dst), "l"(src))
#define CP_COMMIT() asm volatile("cp.async.commit_group;" ::: "memory")
#define CP_WAIT0()  asm volatile("cp.async.wait_group 0;" ::: "memory")
#define CP_WAIT1()  asm volatile("cp.async.wait_group 1;" ::: "memory")

// ===========================================================================
// Converters
// ===========================================================================
__global__ __launch_bounds__(256) void conv_f16(const float* __restrict__ x,
                                                __half* __restrict__ h, int n4)
{
    int i = blockIdx.x * blockDim.x + threadIdx.x;
    if (i >= n4) return;
    float4 v = ((const float4*)x)[i];
    __half2 p0 = __floats2half2_rn(v.x, v.y);
    __half2 p1 = __floats2half2_rn(v.z, v.w);
    uint2 o; o.x = *(uint32_t*)&p0; o.y = *(uint32_t*)&p1;
    ((uint2*)h)[i] = o;
}
__global__ __launch_bounds__(256) void conv_split_f16(const float* __restrict__ x,
                                                      __half* __restrict__ hi,
                                                      __half* __restrict__ lo, int n4)
{
    int i = blockIdx.x * blockDim.x + threadIdx.x;
    if (i >= n4) return;
    float4 v = ((const float4*)x)[i];
    __half h0 = __float2half_rn(v.x), h1 = __float2half_rn(v.y);
    __half h2 = __float2half_rn(v.z), h3 = __float2half_rn(v.w);
    __half l0 = __float2half_rn(v.x - __half2float(h0));
    __half l1 = __float2half_rn(v.y - __half2float(h1));
    __half l2 = __float2half_rn(v.z - __half2float(h2));
    __half l3 = __float2half_rn(v.w - __half2float(h3));
    __half2 hp0(h0, h1), hp1(h2, h3), lp0(l0, l1), lp1(l2, l3);
    uint2 oh, ol;
    oh.x = *(uint32_t*)&hp0; oh.y = *(uint32_t*)&hp1;
    ol.x = *(uint32_t*)&lp0; ol.y = *(uint32_t*)&lp1;
    ((uint2*)hi)[i] = oh;
    ((uint2*)lo)[i] = ol;
}

// ===========================================================================
// Fused RoPE + layout + fp16 convert: Qf (RoPE, *0.125), Kf (RoPE), Vf
// ===========================================================================
__global__ __launch_bounds__(256) void rope_conv(const float* __restrict__ qkv,
                                                 const float* __restrict__ cos_t,
                                                 const float* __restrict__ sin_t,
                                                 __half* __restrict__ qf,
                                                 __half* __restrict__ kf,
                                                 __half* __restrict__ vf)
{
    int idx = blockIdx.x * blockDim.x + threadIdx.x;  // bt*48*32
    int d5   = idx & 31;
    int rest = idx >> 5;
    int head = rest % 48;
    int bt   = rest / 48;
    int t = bt & (TT - 1);
    int b = bt >> 11;
    size_t src = ((size_t)bt * 48 + head) * 64;
    float x1 = qkv[src + d5];
    float x2 = qkv[src + 32 + d5];

    if (head < 32) {
        float c = cos_t[t * 64 + d5];
        float s = sin_t[t * 64 + d5];
        float y1 = x1 * c - x2 * s;
        float y2 = x2 * c + x1 * s;
        if (head < NH) {
            y1 *= 0.125f; y2 *= 0.125f;
            size_t dst = (((size_t)(b * NH + head)) * TT + t) * 64;
            qf[dst + d5]      = __float2half_rn(y1);
            qf[dst + 32 + d5] = __float2half_rn(y2);
        } else {
            size_t dst = (((size_t)(b * NH + head - NH)) * TT + t) * 64;
            kf[dst + d5]      = __float2half_rn(y1);
            kf[dst + 32 + d5] = __float2half_rn(y2);
        }
    } else {
        size_t dst = (((size_t)(b * NH + head - 32)) * TT + t) * 64;
        vf[dst + d5]      = __float2half_rn(x1);
        vf[dst + 32 + d5] = __float2half_rn(x2);
    }
}

// ===========================================================================
// fp16 HMMA GEMMs (round-10, proven): C[.., ldc] = A[M,K] * B[N,K]^T
// ===========================================================================
#define SA 40
#define TSB (128 * SA * 2)
#define BUFB2 (3 * TSB)
#define BUFB1 (2 * TSB)

__global__ __launch_bounds__(256) void gemm_f16x2(const __half* __restrict__ A,
                                                  const __half* __restrict__ Bh,
                                                  const __half* __restrict__ Bl,
                                                  float* __restrict__ C,
                                                  int ldc, int K)
{
    extern __shared__ char dsm[];
    const uint32_t sbase = smem_to_u32(dsm);

    const int tid  = threadIdx.x;
    const int wid  = tid >> 5;
    const int lane = tid & 31;
    const int warp_m = wid >> 2;
    const int warp_n = wid & 3;
    const int bm = blockIdx.y * 128;
    const int bn = blockIdx.x * 128;
    const int lj = lane & 7;
    const int li = lane >> 3;

    float c[4][4][4];
#pragma unroll
    for (int mt = 0; mt < 4; mt++)
#pragma unroll
        for (int nt = 0; nt < 4; nt++)
#pragma unroll
            for (int j = 0; j < 4; j++) c[mt][nt][j] = 0.f;

    const int a_row_base = warp_m * 64 + lj + ((li & 1) << 3);
    const int a_col_base = (li >> 1) << 3;
    const int b_row = warp_n * 32 + li * 8 + lj;

    auto load_chunk = [&](int ch, int buf) {
#pragma unroll
        for (int i = 0; i < 6; i++) {
            const int tile = i >> 1;
            const int v = ((i & 1) << 8) + tid;
            const int r = v >> 2;
            const int c8 = (v & 3) << 3;
            const __half* sp = (tile == 0) ? A : (tile == 1) ? Bh : Bl;
            const int grow = ((tile == 0) ? bm : bn) + r;
            uint32_t dst = sbase + buf * BUFB2 + tile * TSB + (uint32_t)(r * SA + c8) * 2;
            CP_ASYNC16(dst, sp + (size_t)grow * K + ch * 32 + c8);
        }
        CP_COMMIT();
    };

    const int nchunks = K >> 5;
    load_chunk(0, 0);

    for (int ch = 0; ch < nchunks; ch++) {
        const int buf = ch & 1;
        CP_WAIT0();
        __syncthreads();
        if (ch + 1 < nchunks) load_chunk(ch + 1, buf ^ 1);

        const uint32_t base = sbase + buf * BUFB2;
        const uint32_t oBh = TSB, oBl = 2 * TSB;
#pragma unroll
        for (int ks = 0; ks < 2; ks++) {
            const int k0 = ks * 16;
            unsigned bh[2][4], bl[2][4];
#pragma unroll
            for (int kh = 0; kh < 2; kh++) {
                uint32_t ba = base + (uint32_t)(b_row * SA + k0 + kh * 8) * 2;
                ldsm4(bh[kh], oBh + ba);
                ldsm4(bl[kh], oBl + ba);
            }
#pragma unroll
            for (int mt = 0; mt < 4; mt++) {
                unsigned a[4];
                uint32_t aa = base + (uint32_t)((a_row_base + mt * 16) * SA + k0 + a_col_base) * 2;
                ldsm4(a, aa);
#pragma unroll
                for (int nt = 0; nt < 4; nt++) {
                    mma_f16(c[mt][nt], a, bh[0][nt], bh[1][nt]);
                    mma_f16(c[mt][nt], a, bl[0][nt], bl[1][nt]);
                }
            }
        }
    }

    const int q  = lane >> 2;
    const int t4 = lane & 3;
#pragma unroll
    for (int mt = 0; mt < 4; mt++) {
        int row0 = bm + warp_m * 64 + mt * 16 + q;
#pragma unroll
        for (int nt = 0; nt < 4; nt++) {
            int col = bn + warp_n * 32 + nt * 8 + 2 * t4;
            *(float2*)&C[(size_t)row0 * ldc + col] =
                make_float2(c[mt][nt][0], c[mt][nt][1]);
            *(float2*)&C[(size_t)(row0 + 8) * ldc + col] =
                make_float2(c[mt][nt][2], c[mt][nt][3]);
        }
    }
}

__global__ __launch_bounds__(256) void gemm_f16x1(const __half* __restrict__ A,
                                                  const __half* __restrict__ Bm,
                                                  float* __restrict__ C,
                                                  int ldc, int K)
{
    extern __shared__ char dsm[];
    const uint32_t sbase = smem_to_u32(dsm);

    const int tid  = threadIdx.x;
    const int wid  = tid >> 5;
    const int lane = tid & 31;
    const int warp_m = wid >> 2;
    const int warp_n = wid & 3;
    const int bm = blockIdx.y * 128;
    const int bn = blockIdx.x * 128;
    const int lj = lane & 7;
    const int li = lane >> 3;

    float c[4][4][4];
#pragma unroll
    for (int mt = 0; mt < 4; mt++)
#pragma unroll
        for (int nt = 0; nt < 4; nt++)
#pragma unroll
            for (int j = 0; j < 4; j++) c[mt][nt][j] = 0.f;

    const int a_row_base = warp_m * 64 + lj + ((li & 1) << 3);
    const int a_col_base = (li >> 1) << 3;
    const int b_row = warp_n * 32 + li * 8 + lj;

    auto load_chunk = [&](int ch, int buf) {
#pragma unroll
        for (int i = 0; i < 4; i++) {
            const int tile = i >> 1;
            const int v = ((i & 1) << 8) + tid;
            const int r = v >> 2;
            const int c8 = (v & 3) << 3;
            const __half* sp = (tile == 0) ? A : Bm;
            const int grow = ((tile == 0) ? bm : bn) + r;
            uint32_t dst = sbase + buf * BUFB1 + tile * TSB + (uint32_t)(r * SA + c8) * 2;
            CP_ASYNC16(dst, sp + (size_t)grow * K + ch * 32 + c8);
        }
        CP_COMMIT();
    };

    const int nchunks = K >> 5;
    load_chunk(0, 0);

    for (int ch = 0; ch < nchunks; ch++) {
        const int buf = ch & 1;
        CP_WAIT0();
        __syncthreads();
        if (ch + 1 < nchunks) load_chunk(ch + 1, buf ^ 1);

        const uint32_t base = sbase + buf * BUFB1;
        const uint32_t oB = TSB;
#pragma unroll
        for (int ks = 0; ks < 2; ks++) {
            const int k0 = ks * 16;
            unsigned bh[2][4];
#pragma unroll
            for (int kh = 0; kh < 2; kh++) {
                uint32_t ba = base + (uint32_t)(b_row * SA + k0 + kh * 8) * 2;
                ldsm4(bh[kh], oB + ba);
            }
#pragma unroll
            for (int mt = 0; mt < 4; mt++) {
                unsigned a[4];
                uint32_t aa = base + (uint32_t)((a_row_base + mt * 16) * SA + k0 + a_col_base) * 2;
                ldsm4(a, aa);
#pragma unroll
                for (int nt = 0; nt < 4; nt++)
                    mma_f16(c[mt][nt], a, bh[0][nt], bh[1][nt]);
            }
        }
    }

    const int q  = lane >> 2;
    const int t4 = lane & 3;
#pragma unroll
    for (int mt = 0; mt < 4; mt++) {
        int row0 = bm + warp_m * 64 + mt * 16 + q;
#pragma unroll
        for (int nt = 0; nt < 4; nt++) {
            int col = bn + warp_n * 32 + nt * 8 + 2 * t4;
            *(float2*)&C[(size_t)row0 * ldc + col] =
                make_float2(c[mt][nt][0], c[mt][nt][1]);
            *(float2*)&C[(size_t)(row0 + 8) * ldc + col] =
                make_float2(c[mt][nt][2], c[mt][nt][3]);
        }
    }
}

// ===========================================================================
// fp16x1 HMMA flash attention (causal), double-buffered K/V prefetch.
// Block = (64 q-rows, head, batch), 4 warps x 16 rows, Bc=64.
// smem: Q | K0 V0 | K1 V1 = 45 KB static.
// ===========================================================================
#define FSA 72
#define FT (64 * FSA)

__global__ __launch_bounds__(128) void flash_attn_f16(const __half* __restrict__ Qf,
                                                      const __half* __restrict__ Kf,
                                                      const __half* __restrict__ Vf,
                                                      __half* __restrict__ ctx)
{
    __shared__ __half sm_[5 * FT];
    const uint32_t sbase = smem_to_u32(sm_);
    // byte offsets: Q=0; buffer b: K at (1+2b)*FT*2, V at (2+2b)*FT*2

    const int qt = blockIdx.x;
    const int h  = blockIdx.y;
    const int b  = blockIdx.z;
    const int tid  = threadIdx.x;
    const int wid  = tid >> 5;
    const int lane = tid & 31;
    const int lj = lane & 7;
    const int li = lane >> 3;
    const int g  = lane >> 2;
    const int t4 = lane & 3;
    const int wrow = wid * 16;

    const size_t headbase = ((size_t)(b * NH + h)) * TT * 64;

    // KV tile loader into buffer buf (512 x 16B ops, 4/thread)
    auto load_kv = [&](int kt, int buf) {
#pragma unroll
        for (int i = 0; i < 8; i++) {
            int v = i * 128 + tid;
            int tile = v >> 9;          // 0=K 1=V
            int r = (v >> 3) & 63;
            int c8 = (v & 7) << 3;
            const __half* sp = tile ? Vf : Kf;
            uint32_t dst = sbase + (uint32_t)(FT * 2) * (1 + 2 * buf + tile)
                         + (uint32_t)(r * FSA + c8) * 2;
            CP_ASYNC16(dst, sp + headbase + (size_t)(kt * 64 + r) * 64 + c8);
        }
        CP_COMMIT();
    };

    // Q tile (512 x 16B ops) + first KV, one group
#pragma unroll
    for (int i = 0; i < 4; i++) {
        int v = i * 128 + tid;
        int r = v >> 3;
        int c8 = (v & 7) << 3;
        uint32_t dst = sbase + (uint32_t)(r * FSA + c8) * 2;
        CP_ASYNC16(dst, Qf + headbase + (size_t)(qt * 64 + r) * 64 + c8);
    }
    load_kv(0, 0);   // commits Q + KV0 together

    float m0 = -1e30f, m1 = -1e30f, l0 = 0.f, l1 = 0.f;
    float o[8][4];
#pragma unroll
    for (int nt = 0; nt < 8; nt++)
#pragma unroll
        for (int j = 0; j < 4; j++) o[nt][j] = 0.f;

    const int a_row = wrow + lj + ((li & 1) << 3);
    const int a_col = (li >> 1) << 3;
    const int b_row = li * 8 + lj;
    const int v_row = lj + ((li & 1) << 3);
    const int v_col = (lane >> 4) << 3;

    for (int kt = 0; kt <= qt; kt++) {
        const int buf = kt & 1;
        const bool pf = (kt + 1 <= qt);
        if (pf) load_kv(kt + 1, buf ^ 1);
        if (pf) { CP_WAIT1(); } else { CP_WAIT0(); }
        __syncthreads();

        const uint32_t oK = (uint32_t)(FT * 2) * (1 + 2 * buf);
        const uint32_t oV = oK + (uint32_t)(FT * 2);

        // ---- S = Q @ K^T, 1 MMA ----
        float s[8][4];
#pragma unroll
        for (int nt = 0; nt < 8; nt++)
#pragma unroll
            for (int j = 0; j < 4; j++) s[nt][j] = 0.f;

#pragma unroll
        for (int ks = 0; ks < 4; ks++) {
            const int k0 = ks * 16;
            unsigned a[4];
            uint32_t aa = sbase + (uint32_t)(a_row * FSA + k0 + a_col) * 2;
            ldsm4(a, aa);
#pragma unroll
            for (int nh = 0; nh < 2; nh++) {
                unsigned kfr[2][4];
#pragma unroll
                for (int kh = 0; kh < 2; kh++) {
                    uint32_t ba = sbase + oK + (uint32_t)((b_row + nh * 32) * FSA + k0 + kh * 8) * 2;
                    ldsm4(kfr[kh], ba);
                }
#pragma unroll
                for (int nt = 0; nt < 4; nt++)
                    mma_f16(s[nh * 4 + nt], a, kfr[0][nt], kfr[1][nt]);
            }
        }

        // ---- causal mask (diagonal tile) ----
        if (kt == qt) {
            int r0 = wrow + g, r1 = r0 + 8;
#pragma unroll
            for (int nt = 0; nt < 8; nt++) {
                int c0 = nt * 8 + 2 * t4, c1 = c0 + 1;
                if (c0 > r0) s[nt][0] = -1e30f;
                if (c1 > r0) s[nt][1] = -1e30f;
                if (c0 > r1) s[nt][2] = -1e30f;
                if (c1 > r1) s[nt][3] = -1e30f;
            }
        }

        // ---- online softmax ----
        float mx0 = -1e30f, mx1 = -1e30f;
#pragma unroll
        for (int nt = 0; nt < 8; nt++) {
            mx0 = fmaxf(mx0, fmaxf(s[nt][0], s[nt][1]));
            mx1 = fmaxf(mx1, fmaxf(s[nt][2], s[nt][3]));
        }
        mx0 = fmaxf(mx0, __shfl_xor_sync(0xffffffffu, mx0, 1));
        mx0 = fmaxf(mx0, __shfl_xor_sync(0xffffffffu, mx0, 2));
        mx1 = fmaxf(mx1, __shfl_xor_sync(0xffffffffu, mx1, 1));
        mx1 = fmaxf(mx1, __shfl_xor_sync(0xffffffffu, mx1, 2));

        float mn0 = fmaxf(m0, mx0), mn1 = fmaxf(m1, mx1);
        float alpha0 = __expf(m0 - mn0), alpha1 = __expf(m1 - mn1);
        m0 = mn0; m1 = mn1;

        float sum0 = 0.f, sum1 = 0.f;
#pragma unroll
        for (int nt = 0; nt < 8; nt++) {
            s[nt][0] = __expf(s[nt][0] - mn0);
            s[nt][1] = __expf(s[nt][1] - mn0);
            s[nt][2] = __expf(s[nt][2] - mn1);
            s[nt][3] = __expf(s[nt][3] - mn1);
            sum0 += s[nt][0] + s[nt][1];
            sum1 += s[nt][2] + s[nt][3];
        }
        sum0 += __shfl_xor_sync(0xffffffffu, sum0, 1);
        sum0 += __shfl_xor_sync(0xffffffffu, sum0, 2);
        sum1 += __shfl_xor_sync(0xffffffffu, sum1, 1);
        sum1 += __shfl_xor_sync(0xffffffffu, sum1, 2);
        l0 = l0 * alpha0 + sum0;
        l1 = l1 * alpha1 + sum1;

#pragma unroll
        for (int nt = 0; nt < 8; nt++) {
            o[nt][0] *= alpha0; o[nt][1] *= alpha0;
            o[nt][2] *= alpha1; o[nt][3] *= alpha1;
        }

        // ---- O += P @ V, 1 MMA (P fp16) ----
#pragma unroll
        for (int ks = 0; ks < 4; ks++) {
            const int k0 = ks * 16;
            unsigned a[4];
            {
                float* p0 = s[2 * ks];
                float* p1 = s[2 * ks + 1];
                a[0] = pkH(p0[0], p0[1]);
                a[1] = pkH(p0[2], p0[3]);
                a[2] = pkH(p1[0], p1[1]);
                a[3] = pkH(p1[2], p1[3]);
            }
#pragma unroll
            for (int nh = 0; nh < 4; nh++) {
                uint32_t va = sbase + oV + (uint32_t)((k0 + v_row) * FSA + nh * 16 + v_col) * 2;
                unsigned vfr[4];
                ldsm4t(vfr, va);
                mma_f16(o[nh * 2],     a, vfr[0], vfr[1]);
                mma_f16(o[nh * 2 + 1], a, vfr[2], vfr[3]);
            }
        }
        __syncthreads();   // all warps done with buf before next prefetch overwrites it
    }

    // ---- epilogue ----
    float inv0 = 1.f / l0, inv1 = 1.f / l1;
    int row0 = qt * 64 + wrow + g;
    size_t base0 = ((size_t)(b * TT + row0)) * HIDDEN + h * 64;
    size_t base1 = base0 + 8 * HIDDEN;
#pragma unroll
    for (int nt = 0; nt < 8; nt++) {
        int c = nt * 8 + 2 * t4;
        __half2 p0 = __floats2half2_rn(o[nt][0] * inv0, o[nt][1] * inv0);
        __half2 p1 = __floats2half2_rn(o[nt][2] * inv1, o[nt][3] * inv1);
        *(unsigned*)&ctx[base0 + c] = *(unsigned*)&p0;
        *(unsigned*)&ctx[base1 + c] = *(unsigned*)&p1;
    }
}

// ---------------------------------------------------------------------------
extern "C" void kernel_launch(void* const* d_in, const int* in_sizes, int n_in,
                              void* d_out, int out_size)
{
    const float* hs    = (const float*)d_in[0];
    const float* cos_t = (const float*)d_in[1];
    const float* sin_t = (const float*)d_in[2];
    const float* wqkv  = (const float*)d_in[3];
    const float* wo    = (const float*)d_in[4];
    float* out = (float*)d_out;

    float* qkv = nullptr;
    __half *hs_f, *wq_h, *wq_l, *wo_h, *ctx, *qf, *kf, *vf;
    cudaGetSymbolAddress((void**)&qkv,  g_qkv);
    cudaGetSymbolAddress((void**)&hs_f, g_hs_f);
    cudaGetSymbolAddress((void**)&wq_h, g_wq_h);
    cudaGetSymbolAddress((void**)&wq_l, g_wq_l);
    cudaGetSymbolAddress((void**)&wo_h, g_wo_h);
    cudaGetSymbolAddress((void**)&ctx,  g_ctx);
    cudaGetSymbolAddress((void**)&qf,   g_qf);
    cudaGetSymbolAddress((void**)&kf,   g_kf);
    cudaGetSymbolAddress((void**)&vf,   g_vf);

    // 0) converts
    conv_f16<<<MROWS * HIDDEN / 4 / 256, 256>>>(hs, hs_f, MROWS * HIDDEN / 4);
    conv_split_f16<<<QKV_O * HIDDEN / 4 / 256, 256>>>(wqkv, wq_h, wq_l, QKV_O * HIDDEN / 4);
    conv_f16<<<HIDDEN * HIDDEN / 4 / 256, 256>>>(wo, wo_h, HIDDEN * HIDDEN / 4);

    cudaFuncSetAttribute(gemm_f16x2, cudaFuncAttributeMaxDynamicSharedMemorySize, 2 * BUFB2);
    cudaFuncSetAttribute(gemm_f16x1, cudaFuncAttributeMaxDynamicSharedMemorySize, 2 * BUFB1);

    // 1a) Q columns of QKV (x2 weights)
    gemm_f16x2<<<dim3(8, MROWS / 128), 256, 2 * BUFB2>>>(
        hs_f, wq_h, wq_l, qkv, QKV_O, HIDDEN);
    // 1b) K,V columns of QKV (x1 weights)
    gemm_f16x1<<<dim3(16, MROWS / 128), 256, 2 * BUFB1>>>(
        hs_f, wq_h + (size_t)HIDDEN * HIDDEN, qkv + HIDDEN, QKV_O, HIDDEN);

    // 2) Fused RoPE + fp16 head-major layout
    rope_conv<<<(MROWS * 48 * 32) / 256, 256>>>(qkv, cos_t, sin_t, qf, kf, vf);

    // 3) Flash attention (fp16 x1 HMMA, double-buffered K/V)
    flash_attn_f16<<<dim3(TT / 64, NH, BB), 128>>>(qf, kf, vf, ctx);

    // 4) out = ctx @ wo^T (x1 weights)
    gemm_f16x1<<<dim3(8, MROWS / 128), 256, 2 * BUFB1>>>(
        ctx, wo_h, out, HIDDEN, HIDDEN);
}

// round 12
// speedup vs baseline: 2.1902x; 1.1119x over previous
#include <cuda_runtime.h>
#include <cuda_bf16.h>
#include <cuda_fp16.h>
#include <cstdint>
#include <math.h>

#define BB 2
#define TT 2048
#define HIDDEN 1024
#define NH 16
#define QKV_O 3072   // (16 + 2*16) * 64
#define MROWS (BB*TT) // 4096

// Scratch (allocation-free rule: __device__ globals)
__device__ float g_qkv[(size_t)MROWS * QKV_O];            // [B*T, 3072] fp32
__device__ __half g_hs_f[(size_t)MROWS * HIDDEN];
__device__ __half g_wq_h[(size_t)QKV_O * HIDDEN];
__device__ __half g_wo_h[(size_t)HIDDEN * HIDDEN];
__device__ __half g_ctx[(size_t)MROWS * HIDDEN];
// head-major fp16 attention operands: [b, h, t, d]
__device__ __half g_qf[(size_t)BB * NH * TT * 64];
__device__ __half g_kf[(size_t)BB * NH * TT * 64];
__device__ __half g_vf[(size_t)BB * NH * TT * 64];

// ===========================================================================
// Helpers
// ===========================================================================
__device__ __forceinline__ uint32_t smem_to_u32(const void* p) {
    uint32_t a;
    asm("{ .reg .u64 t; cvta.to.shared.u64 t, %1; cvt.u32.u64 %0, t; }" : "=r"(a) : "l"(p));
    return a;
}
__device__ __forceinline__ void ldsm4(unsigned* r, uint32_t addr) {
    asm volatile("ldmatrix.sync.aligned.m8n8.x4.shared.b16 {%0,%1,%2,%3}, [%4];"
                 : "=r"(r[0]), "=r"(r[1]), "=r"(r[2]), "=r"(r[3]) : "r"(addr));
}
__device__ __forceinline__ void ldsm4t(unsigned* r, uint32_t addr) {
    asm volatile("ldmatrix.sync.aligned.m8n8.x4.trans.shared.b16 {%0,%1,%2,%3}, [%4];"
                 : "=r"(r[0]), "=r"(r[1]), "=r"(r[2]), "=r"(r[3]) : "r"(addr));
}
__device__ __forceinline__ void mma_f16(float* c, const unsigned* a, unsigned b0, unsigned b1) {
    asm volatile("mma.sync.aligned.m16n8k16.row.col.f32.f16.f16.f32 "
                 "{%0,%1,%2,%3}, {%4,%5,%6,%7}, {%8,%9}, {%0,%1,%2,%3};"
                 : "+f"(c[0]), "+f"(c[1]), "+f"(c[2]), "+f"(c[3])
                 : "r"(a[0]), "r"(a[1]), "r"(a[2]), "r"(a[3]), "r"(b0), "r"(b1));
}
__device__ __forceinline__ unsigned pkH(float x, float y) {
    __half2 p(__float2half_rn(x), __float2half_rn(y));
    return *(unsigned*)&p;
}
#define CP_ASYNC16(dst, src) \
    asm volatile("cp.async.cg.shared.global [%0], [%1], 16;" :: "r"(dst), "l"(src))
#define CP_COMMIT() asm volatile("cp.async.commit_group;" ::: "memory")
#define CP_WAIT0()  asm volatile("cp.async.wait_group 0;" ::: "memory")
#define CP_WAIT1()  asm volatile("cp.async.wait_group 1;" ::: "memory")

// ===========================================================================
// Converter (fp32 -> fp16)
// ===========================================================================
__global__ __launch_bounds__(256) void conv_f16(const float* __restrict__ x,
                                                __half* __restrict__ h, int n4)
{
    int i = blockIdx.x * blockDim.x + threadIdx.x;
    if (i >= n4) return;
    float4 v = ((const float4*)x)[i];
    __half2 p0 = __floats2half2_rn(v.x, v.y);
    __half2 p1 = __floats2half2_rn(v.z, v.w);
    uint2 o; o.x = *(uint32_t*)&p0; o.y = *(uint32_t*)&p1;
    ((uint2*)h)[i] = o;
}

// ===========================================================================
// Fused RoPE + layout + fp16 convert: Qf (RoPE, *0.125), Kf (RoPE), Vf
// ===========================================================================
__global__ __launch_bounds__(256) void rope_conv(const float* __restrict__ qkv,
                                                 const float* __restrict__ cos_t,
                                                 const float* __restrict__ sin_t,
                                                 __half* __restrict__ qf,
                                                 __half* __restrict__ kf,
                                                 __half* __restrict__ vf)
{
    int idx = blockIdx.x * blockDim.x + threadIdx.x;  // bt*48*32
    int d5   = idx & 31;
    int rest = idx >> 5;
    int head = rest % 48;
    int bt   = rest / 48;
    int t = bt & (TT - 1);
    int b = bt >> 11;
    size_t src = ((size_t)bt * 48 + head) * 64;
    float x1 = qkv[src + d5];
    float x2 = qkv[src + 32 + d5];

    if (head < 32) {
        float c = cos_t[t * 64 + d5];
        float s = sin_t[t * 64 + d5];
        float y1 = x1 * c - x2 * s;
        float y2 = x2 * c + x1 * s;
        if (head < NH) {
            y1 *= 0.125f; y2 *= 0.125f;
            size_t dst = (((size_t)(b * NH + head)) * TT + t) * 64;
            qf[dst + d5]      = __float2half_rn(y1);
            qf[dst + 32 + d5] = __float2half_rn(y2);
        } else {
            size_t dst = (((size_t)(b * NH + head - NH)) * TT + t) * 64;
            kf[dst + d5]      = __float2half_rn(y1);
            kf[dst + 32 + d5] = __float2half_rn(y2);
        }
    } else {
        size_t dst = (((size_t)(b * NH + head - 32)) * TT + t) * 64;
        vf[dst + d5]      = __float2half_rn(x1);
        vf[dst + 32 + d5] = __float2half_rn(x2);
    }
}

// ===========================================================================
// fp16x1 HMMA GEMM (proven): C[.., ldc] = A[M,K] * B[N,K]^T
// 128x128 tile, BK=32, 8 warps, cp.async double-buffered.
// ===========================================================================
#define SA 40
#define TSB (128 * SA * 2)
#define BUFB1 (2 * TSB)

__global__ __launch_bounds__(256) void gemm_f16x1(const __half* __restrict__ A,
                                                  const __half* __restrict__ Bm,
                                                  float* __restrict__ C,
                                                  int ldc, int K)
{
    extern __shared__ char dsm[];
    const uint32_t sbase = smem_to_u32(dsm);

    const int tid  = threadIdx.x;
    const int wid  = tid >> 5;
    const int lane = tid & 31;
    const int warp_m = wid >> 2;
    const int warp_n = wid & 3;
    const int bm = blockIdx.y * 128;
    const int bn = blockIdx.x * 128;
    const int lj = lane & 7;
    const int li = lane >> 3;

    float c[4][4][4];
#pragma unroll
    for (int mt = 0; mt < 4; mt++)
#pragma unroll
        for (int nt = 0; nt < 4; nt++)
#pragma unroll
            for (int j = 0; j < 4; j++) c[mt][nt][j] = 0.f;

    const int a_row_base = warp_m * 64 + lj + ((li & 1) << 3);
    const int a_col_base = (li >> 1) << 3;
    const int b_row = warp_n * 32 + li * 8 + lj;

    auto load_chunk = [&](int ch, int buf) {
#pragma unroll
        for (int i = 0; i < 4; i++) {
            const int tile = i >> 1;
            const int v = ((i & 1) << 8) + tid;
            const int r = v >> 2;
            const int c8 = (v & 3) << 3;
            const __half* sp = (tile == 0) ? A : Bm;
            const int grow = ((tile == 0) ? bm : bn) + r;
            uint32_t dst = sbase + buf * BUFB1 + tile * TSB + (uint32_t)(r * SA + c8) * 2;
            CP_ASYNC16(dst, sp + (size_t)grow * K + ch * 32 + c8);
        }
        CP_COMMIT();
    };

    const int nchunks = K >> 5;
    load_chunk(0, 0);

    for (int ch = 0; ch < nchunks; ch++) {
        const int buf = ch & 1;
        CP_WAIT0();
        __syncthreads();
        if (ch + 1 < nchunks) load_chunk(ch + 1, buf ^ 1);

        const uint32_t base = sbase + buf * BUFB1;
        const uint32_t oB = TSB;
#pragma unroll
        for (int ks = 0; ks < 2; ks++) {
            const int k0 = ks * 16;
            unsigned bh[2][4];
#pragma unroll
            for (int kh = 0; kh < 2; kh++) {
                uint32_t ba = base + (uint32_t)(b_row * SA + k0 + kh * 8) * 2;
                ldsm4(bh[kh], oB + ba);
            }
#pragma unroll
            for (int mt = 0; mt < 4; mt++) {
                unsigned a[4];
                uint32_t aa = base + (uint32_t)((a_row_base + mt * 16) * SA + k0 + a_col_base) * 2;
                ldsm4(a, aa);
#pragma unroll
                for (int nt = 0; nt < 4; nt++)
                    mma_f16(c[mt][nt], a, bh[0][nt], bh[1][nt]);
            }
        }
    }

    const int q  = lane >> 2;
    const int t4 = lane & 3;
#pragma unroll
    for (int mt = 0; mt < 4; mt++) {
        int row0 = bm + warp_m * 64 + mt * 16 + q;
#pragma unroll
        for (int nt = 0; nt < 4; nt++) {
            int col = bn + warp_n * 32 + nt * 8 + 2 * t4;
            *(float2*)&C[(size_t)row0 * ldc + col] =
                make_float2(c[mt][nt][0], c[mt][nt][1]);
            *(float2*)&C[(size_t)(row0 + 8) * ldc + col] =
                make_float2(c[mt][nt][2], c[mt][nt][3]);
        }
    }
}

// ===========================================================================
// fp16x1 HMMA flash attention (round-11, proven), double-buffered K/V.
// ===========================================================================
#define FSA 72
#define FT (64 * FSA)

__global__ __launch_bounds__(128) void flash_attn_f16(const __half* __restrict__ Qf,
                                                      const __half* __restrict__ Kf,
                                                      const __half* __restrict__ Vf,
                                                      __half* __restrict__ ctx)
{
    __shared__ __half sm_[5 * FT];
    const uint32_t sbase = smem_to_u32(sm_);

    const int qt = blockIdx.x;
    const int h  = blockIdx.y;
    const int b  = blockIdx.z;
    const int tid  = threadIdx.x;
    const int wid  = tid >> 5;
    const int lane = tid & 31;
    const int lj = lane & 7;
    const int li = lane >> 3;
    const int g  = lane >> 2;
    const int t4 = lane & 3;
    const int wrow = wid * 16;

    const size_t headbase = ((size_t)(b * NH + h)) * TT * 64;

    auto load_kv = [&](int kt, int buf) {
#pragma unroll
        for (int i = 0; i < 8; i++) {
            int v = i * 128 + tid;
            int tile = v >> 9;
            int r = (v >> 3) & 63;
            int c8 = (v & 7) << 3;
            const __half* sp = tile ? Vf : Kf;
            uint32_t dst = sbase + (uint32_t)(FT * 2) * (1 + 2 * buf + tile)
                         + (uint32_t)(r * FSA + c8) * 2;
            CP_ASYNC16(dst, sp + headbase + (size_t)(kt * 64 + r) * 64 + c8);
        }
        CP_COMMIT();
    };

#pragma unroll
    for (int i = 0; i < 4; i++) {
        int v = i * 128 + tid;
        int r = v >> 3;
        int c8 = (v & 7) << 3;
        uint32_t dst = sbase + (uint32_t)(r * FSA + c8) * 2;
        CP_ASYNC16(dst, Qf + headbase + (size_t)(qt * 64 + r) * 64 + c8);
    }
    load_kv(0, 0);

    float m0 = -1e30f, m1 = -1e30f, l0 = 0.f, l1 = 0.f;
    float o[8][4];
#pragma unroll
    for (int nt = 0; nt < 8; nt++)
#pragma unroll
        for (int j = 0; j < 4; j++) o[nt][j] = 0.f;

    const int a_row = wrow + lj + ((li & 1) << 3);
    const int a_col = (li >> 1) << 3;
    const int b_row = li * 8 + lj;
    const int v_row = lj + ((li & 1) << 3);
    const int v_col = (lane >> 4) << 3;

    for (int kt = 0; kt <= qt; kt++) {
        const int buf = kt & 1;
        const bool pf = (kt + 1 <= qt);
        if (pf) load_kv(kt + 1, buf ^ 1);
        if (pf) { CP_WAIT1(); } else { CP_WAIT0(); }
        __syncthreads();

        const uint32_t oK = (uint32_t)(FT * 2) * (1 + 2 * buf);
        const uint32_t oV = oK + (uint32_t)(FT * 2);

        float s[8][4];
#pragma unroll
        for (int nt = 0; nt < 8; nt++)
#pragma unroll
            for (int j = 0; j < 4; j++) s[nt][j] = 0.f;

#pragma unroll
        for (int ks = 0; ks < 4; ks++) {
            const int k0 = ks * 16;
            unsigned a[4];
            uint32_t aa = sbase + (uint32_t)(a_row * FSA + k0 + a_col) * 2;
            ldsm4(a, aa);
#pragma unroll
            for (int nh = 0; nh < 2; nh++) {
                unsigned kfr[2][4];
#pragma unroll
                for (int kh = 0; kh < 2; kh++) {
                    uint32_t ba = sbase + oK + (uint32_t)((b_row + nh * 32) * FSA + k0 + kh * 8) * 2;
                    ldsm4(kfr[kh], ba);
                }
#pragma unroll
                for (int nt = 0; nt < 4; nt++)
                    mma_f16(s[nh * 4 + nt], a, kfr[0][nt], kfr[1][nt]);
            }
        }

        if (kt == qt) {
            int r0 = wrow + g, r1 = r0 + 8;
#pragma unroll
            for (int nt = 0; nt < 8; nt++) {
                int c0 = nt * 8 + 2 * t4, c1 = c0 + 1;
                if (c0 > r0) s[nt][0] = -1e30f;
                if (c1 > r0) s[nt][1] = -1e30f;
                if (c0 > r1) s[nt][2] = -1e30f;
                if (c1 > r1) s[nt][3] = -1e30f;
            }
        }

        float mx0 = -1e30f, mx1 = -1e30f;
#pragma unroll
        for (int nt = 0; nt < 8; nt++) {
            mx0 = fmaxf(mx0, fmaxf(s[nt][0], s[nt][1]));
            mx1 = fmaxf(mx1, fmaxf(s[nt][2], s[nt][3]));
        }
        mx0 = fmaxf(mx0, __shfl_xor_sync(0xffffffffu, mx0, 1));
        mx0 = fmaxf(mx0, __shfl_xor_sync(0xffffffffu, mx0, 2));
        mx1 = fmaxf(mx1, __shfl_xor_sync(0xffffffffu, mx1, 1));
        mx1 = fmaxf(mx1, __shfl_xor_sync(0xffffffffu, mx1, 2));

        float mn0 = fmaxf(m0, mx0), mn1 = fmaxf(m1, mx1);
        float alpha0 = __expf(m0 - mn0), alpha1 = __expf(m1 - mn1);
        m0 = mn0; m1 = mn1;

        float sum0 = 0.f, sum1 = 0.f;
#pragma unroll
        for (int nt = 0; nt < 8; nt++) {
            s[nt][0] = __expf(s[nt][0] - mn0);
            s[nt][1] = __expf(s[nt][1] - mn0);
            s[nt][2] = __expf(s[nt][2] - mn1);
            s[nt][3] = __expf(s[nt][3] - mn1);
            sum0 += s[nt][0] + s[nt][1];
            sum1 += s[nt][2] + s[nt][3];
        }
        sum0 += __shfl_xor_sync(0xffffffffu, sum0, 1);
        sum0 += __shfl_xor_sync(0xffffffffu, sum0, 2);
        sum1 += __shfl_xor_sync(0xffffffffu, sum1, 1);
        sum1 += __shfl_xor_sync(0xffffffffu, sum1, 2);
        l0 = l0 * alpha0 + sum0;
        l1 = l1 * alpha1 + sum1;

#pragma unroll
        for (int nt = 0; nt < 8; nt++) {
            o[nt][0] *= alpha0; o[nt][1] *= alpha0;
            o[nt][2] *= alpha1; o[nt][3] *= alpha1;
        }

#pragma unroll
        for (int ks = 0; ks < 4; ks++) {
            const int k0 = ks * 16;
            unsigned a[4];
            {
                float* p0 = s[2 * ks];
                float* p1 = s[2 * ks + 1];
                a[0] = pkH(p0[0], p0[1]);
                a[1] = pkH(p0[2], p0[3]);
                a[2] = pkH(p1[0], p1[1]);
                a[3] = pkH(p1[2], p1[3]);
            }
#pragma unroll
            for (int nh = 0; nh < 4; nh++) {
                uint32_t va = sbase + oV + (uint32_t)((k0 + v_row) * FSA + nh * 16 + v_col) * 2;
                unsigned vfr[4];
                ldsm4t(vfr, va);
                mma_f16(o[nh * 2],     a, vfr[0], vfr[1]);
                mma_f16(o[nh * 2 + 1], a, vfr[2], vfr[3]);
            }
        }
        __syncthreads();
    }

    float inv0 = 1.f / l0, inv1 = 1.f / l1;
    int row0 = qt * 64 + wrow + g;
    size_t base0 = ((size_t)(b * TT + row0)) * HIDDEN + h * 64;
    size_t base1 = base0 + 8 * HIDDEN;
#pragma unroll
    for (int nt = 0; nt < 8; nt++) {
        int c = nt * 8 + 2 * t4;
        __half2 p0 = __floats2half2_rn(o[nt][0] * inv0, o[nt][1] * inv0);
        __half2 p1 = __floats2half2_rn(o[nt][2] * inv1, o[nt][3] * inv1);
        *(unsigned*)&ctx[base0 + c] = *(unsigned*)&p0;
        *(unsigned*)&ctx[base1 + c] = *(unsigned*)&p1;
    }
}

// ---------------------------------------------------------------------------
extern "C" void kernel_launch(void* const* d_in, const int* in_sizes, int n_in,
                              void* d_out, int out_size)
{
    const float* hs    = (const float*)d_in[0];
    const float* cos_t = (const float*)d_in[1];
    const float* sin_t = (const float*)d_in[2];
    const float* wqkv  = (const float*)d_in[3];
    const float* wo    = (const float*)d_in[4];
    float* out = (float*)d_out;

    float* qkv = nullptr;
    __half *hs_f, *wq_h, *wo_h, *ctx, *qf, *kf, *vf;
    cudaGetSymbolAddress((void**)&qkv,  g_qkv);
    cudaGetSymbolAddress((void**)&hs_f, g_hs_f);
    cudaGetSymbolAddress((void**)&wq_h, g_wq_h);
    cudaGetSymbolAddress((void**)&wo_h, g_wo_h);
    cudaGetSymbolAddress((void**)&ctx,  g_ctx);
    cudaGetSymbolAddress((void**)&qf,   g_qf);
    cudaGetSymbolAddress((void**)&kf,   g_kf);
    cudaGetSymbolAddress((void**)&vf,   g_vf);

    // 0) converts (all plain fp16 now)
    conv_f16<<<MROWS * HIDDEN / 4 / 256, 256>>>(hs, hs_f, MROWS * HIDDEN / 4);
    conv_f16<<<QKV_O * HIDDEN / 4 / 256, 256>>>(wqkv, wq_h, QKV_O * HIDDEN / 4);
    conv_f16<<<HIDDEN * HIDDEN / 4 / 256, 256>>>(wo, wo_h, HIDDEN * HIDDEN / 4);

    cudaFuncSetAttribute(gemm_f16x1, cudaFuncAttributeMaxDynamicSharedMemorySize, 2 * BUFB1);

    // 1) QKV = hs @ wqkv^T  (single x1 GEMM, N=3072)
    gemm_f16x1<<<dim3(QKV_O / 128, MROWS / 128), 256, 2 * BUFB1>>>(
        hs_f, wq_h, qkv, QKV_O, HIDDEN);

    // 2) Fused RoPE + fp16 head-major layout
    rope_conv<<<(MROWS * 48 * 32) / 256, 256>>>(qkv, cos_t, sin_t, qf, kf, vf);

    // 3) Flash attention (fp16 x1 HMMA, double-buffered K/V)
    flash_attn_f16<<<dim3(TT / 64, NH, BB), 128>>>(qf, kf, vf, ctx);

    // 4) out = ctx @ wo^T (x1 weights)
    gemm_f16x1<<<dim3(8, MROWS / 128), 256, 2 * BUFB1>>>(
        ctx, wo_h, out, HIDDEN, HIDDEN);
}

// round 13
// speedup vs baseline: 2.2246x; 1.0157x over previous
#include <cuda_runtime.h>
#include <cuda_bf16.h>
#include <cuda_fp16.h>
#include <cstdint>
#include <math.h>

#define BB 2
#define TT 2048
#define HIDDEN 1024
#define NH 16
#define QKV_O 3072   // (16 + 2*16) * 64
#define MROWS (BB*TT) // 4096

// Scratch (allocation-free rule: __device__ globals)
__device__ float g_qkv[(size_t)MROWS * QKV_O];            // [B*T, 3072] fp32
__device__ __half g_hs_f[(size_t)MROWS * HIDDEN];
__device__ __half g_wq_h[(size_t)QKV_O * HIDDEN];
__device__ __half g_wo_h[(size_t)HIDDEN * HIDDEN];
__device__ __half g_ctx[(size_t)MROWS * HIDDEN];
// head-major fp16 attention operands: [b, h, t, d]
__device__ __half g_qf[(size_t)BB * NH * TT * 64];
__device__ __half g_kf[(size_t)BB * NH * TT * 64];
__device__ __half g_vf[(size_t)BB * NH * TT * 64];

// ===========================================================================
// Helpers
// ===========================================================================
__device__ __forceinline__ uint32_t smem_to_u32(const void* p) {
    uint32_t a;
    asm("{ .reg .u64 t; cvta.to.shared.u64 t, %1; cvt.u32.u64 %0, t; }" : "=r"(a) : "l"(p));
    return a;
}
__device__ __forceinline__ void ldsm4(unsigned* r, uint32_t addr) {
    asm volatile("ldmatrix.sync.aligned.m8n8.x4.shared.b16 {%0,%1,%2,%3}, [%4];"
                 : "=r"(r[0]), "=r"(r[1]), "=r"(r[2]), "=r"(r[3]) : "r"(addr));
}
__device__ __forceinline__ void ldsm4t(unsigned* r, uint32_t addr) {
    asm volatile("ldmatrix.sync.aligned.m8n8.x4.trans.shared.b16 {%0,%1,%2,%3}, [%4];"
                 : "=r"(r[0]), "=r"(r[1]), "=r"(r[2]), "=r"(r[3]) : "r"(addr));
}
__device__ __forceinline__ void mma_f16(float* c, const unsigned* a, unsigned b0, unsigned b1) {
    asm volatile("mma.sync.aligned.m16n8k16.row.col.f32.f16.f16.f32 "
                 "{%0,%1,%2,%3}, {%4,%5,%6,%7}, {%8,%9}, {%0,%1,%2,%3};"
                 : "+f"(c[0]), "+f"(c[1]), "+f"(c[2]), "+f"(c[3])
                 : "r"(a[0]), "r"(a[1]), "r"(a[2]), "r"(a[3]), "r"(b0), "r"(b1));
}
__device__ __forceinline__ unsigned pkH(float x, float y) {
    __half2 p(__float2half_rn(x), __float2half_rn(y));
    return *(unsigned*)&p;
}
#define CP_ASYNC16(dst, src) \
    asm volatile("cp.async.cg.shared.global [%0], [%1], 16;" :: "r"(dst), "l"(src))
#define CP_COMMIT() asm volatile("cp.async.commit_group;" ::: "memory")
#define CP_WAIT0()  asm volatile("cp.async.wait_group 0;" ::: "memory")
#define CP_WAIT1()  asm volatile("cp.async.wait_group 1;" ::: "memory")

// ===========================================================================
// Converter (fp32 -> fp16)
// ===========================================================================
__global__ __launch_bounds__(256) void conv_f16(const float* __restrict__ x,
                                                __half* __restrict__ h, int n4)
{
    int i = blockIdx.x * blockDim.x + threadIdx.x;
    if (i >= n4) return;
    float4 v = ((const float4*)x)[i];
    __half2 p0 = __floats2half2_rn(v.x, v.y);
    __half2 p1 = __floats2half2_rn(v.z, v.w);
    uint2 o; o.x = *(uint32_t*)&p0; o.y = *(uint32_t*)&p1;
    ((uint2*)h)[i] = o;
}

// ===========================================================================
// Fused RoPE + layout + fp16 convert: Qf (RoPE, *0.125), Kf (RoPE), Vf
// ===========================================================================
__global__ __launch_bounds__(256) void rope_conv(const float* __restrict__ qkv,
                                                 const float* __restrict__ cos_t,
                                                 const float* __restrict__ sin_t,
                                                 __half* __restrict__ qf,
                                                 __half* __restrict__ kf,
                                                 __half* __restrict__ vf)
{
    int idx = blockIdx.x * blockDim.x + threadIdx.x;  // bt*48*32
    int d5   = idx & 31;
    int rest = idx >> 5;
    int head = rest % 48;
    int bt   = rest / 48;
    int t = bt & (TT - 1);
    int b = bt >> 11;
    size_t src = ((size_t)bt * 48 + head) * 64;
    float x1 = qkv[src + d5];
    float x2 = qkv[src + 32 + d5];

    if (head < 32) {
        float c = cos_t[t * 64 + d5];
        float s = sin_t[t * 64 + d5];
        float y1 = x1 * c - x2 * s;
        float y2 = x2 * c + x1 * s;
        if (head < NH) {
            y1 *= 0.125f; y2 *= 0.125f;
            size_t dst = (((size_t)(b * NH + head)) * TT + t) * 64;
            qf[dst + d5]      = __float2half_rn(y1);
            qf[dst + 32 + d5] = __float2half_rn(y2);
        } else {
            size_t dst = (((size_t)(b * NH + head - NH)) * TT + t) * 64;
            kf[dst + d5]      = __float2half_rn(y1);
            kf[dst + 32 + d5] = __float2half_rn(y2);
        }
    } else {
        size_t dst = (((size_t)(b * NH + head - 32)) * TT + t) * 64;
        vf[dst + d5]      = __float2half_rn(x1);
        vf[dst + 32 + d5] = __float2half_rn(x2);
    }
}

// ===========================================================================
// fp16x1 HMMA GEMM, 64x64 warp tile: C[.., ldc] = A[M,K] * B[N,K]^T
// 128x128 CTA tile, BK=32, 4 warps (64x64 each), cp.async double-buffered.
// Per k16: 8 ldsm4 feed 32 MMAs (mma:ldsm = 4).
// ===========================================================================
#define SA 40
#define TSB (128 * SA * 2)
#define BUFB1 (2 * TSB)

__global__ __launch_bounds__(128, 2) void gemm_f16w64(const __half* __restrict__ A,
                                                      const __half* __restrict__ Bm,
                                                      float* __restrict__ C,
                                                      int ldc, int K)
{
    extern __shared__ char dsm[];
    const uint32_t sbase = smem_to_u32(dsm);

    const int tid  = threadIdx.x;
    const int wid  = tid >> 5;
    const int lane = tid & 31;
    const int warp_m = wid >> 1;      // 0..1
    const int warp_n = wid & 1;       // 0..1
    const int bm = blockIdx.y * 128;
    const int bn = blockIdx.x * 128;
    const int lj = lane & 7;
    const int li = lane >> 3;

    float c[4][8][4];
#pragma unroll
    for (int mt = 0; mt < 4; mt++)
#pragma unroll
        for (int nt = 0; nt < 8; nt++)
#pragma unroll
            for (int j = 0; j < 4; j++) c[mt][nt][j] = 0.f;

    const int a_row_base = warp_m * 64 + lj + ((li & 1) << 3);
    const int a_col_base = (li >> 1) << 3;
    const int b_row = warp_n * 64 + li * 8 + lj;

    // 2 tiles x 512 16B ops = 1024 ops / 128 threads = 8 per thread
    auto load_chunk = [&](int ch, int buf) {
#pragma unroll
        for (int i = 0; i < 8; i++) {
            const int tile = i >> 2;                  // 0=A 1=B
            const int v = ((i & 3) << 7) + tid;       // 0..511
            const int r = v >> 2;
            const int c8 = (v & 3) << 3;
            const __half* sp = (tile == 0) ? A : Bm;
            const int grow = ((tile == 0) ? bm : bn) + r;
            uint32_t dst = sbase + buf * BUFB1 + tile * TSB + (uint32_t)(r * SA + c8) * 2;
            CP_ASYNC16(dst, sp + (size_t)grow * K + ch * 32 + c8);
        }
        CP_COMMIT();
    };

    const int nchunks = K >> 5;
    load_chunk(0, 0);

    for (int ch = 0; ch < nchunks; ch++) {
        const int buf = ch & 1;
        CP_WAIT0();
        __syncthreads();
        if (ch + 1 < nchunks) load_chunk(ch + 1, buf ^ 1);

        const uint32_t base = sbase + buf * BUFB1;
        const uint32_t oB = TSB;
#pragma unroll
        for (int ks = 0; ks < 2; ks++) {
            const int k0 = ks * 16;
            unsigned bf[2][2][4];     // [nh][kh][nt]
#pragma unroll
            for (int nh = 0; nh < 2; nh++)
#pragma unroll
                for (int kh = 0; kh < 2; kh++) {
                    uint32_t ba = base + oB
                        + (uint32_t)((b_row + nh * 32) * SA + k0 + kh * 8) * 2;
                    ldsm4(bf[nh][kh], ba);
                }
#pragma unroll
            for (int mt = 0; mt < 4; mt++) {
                unsigned a[4];
                uint32_t aa = base + (uint32_t)((a_row_base + mt * 16) * SA + k0 + a_col_base) * 2;
                ldsm4(a, aa);
#pragma unroll
                for (int nh = 0; nh < 2; nh++)
#pragma unroll
                    for (int nt = 0; nt < 4; nt++)
                        mma_f16(c[mt][nh * 4 + nt], a, bf[nh][0][nt], bf[nh][1][nt]);
            }
        }
    }

    const int q  = lane >> 2;
    const int t4 = lane & 3;
#pragma unroll
    for (int mt = 0; mt < 4; mt++) {
        int row0 = bm + warp_m * 64 + mt * 16 + q;
#pragma unroll
        for (int nt = 0; nt < 8; nt++) {
            int col = bn + warp_n * 64 + nt * 8 + 2 * t4;
            *(float2*)&C[(size_t)row0 * ldc + col] =
                make_float2(c[mt][nt][0], c[mt][nt][1]);
            *(float2*)&C[(size_t)(row0 + 8) * ldc + col] =
                make_float2(c[mt][nt][2], c[mt][nt][3]);
        }
    }
}

// ===========================================================================
// fp16x1 HMMA flash attention (round-11, proven), double-buffered K/V.
// ===========================================================================
#define FSA 72
#define FT (64 * FSA)

__global__ __launch_bounds__(128) void flash_attn_f16(const __half* __restrict__ Qf,
                                                      const __half* __restrict__ Kf,
                                                      const __half* __restrict__ Vf,
                                                      __half* __restrict__ ctx)
{
    __shared__ __half sm_[5 * FT];
    const uint32_t sbase = smem_to_u32(sm_);

    const int qt = blockIdx.x;
    const int h  = blockIdx.y;
    const int b  = blockIdx.z;
    const int tid  = threadIdx.x;
    const int wid  = tid >> 5;
    const int lane = tid & 31;
    const int lj = lane & 7;
    const int li = lane >> 3;
    const int g  = lane >> 2;
    const int t4 = lane & 3;
    const int wrow = wid * 16;

    const size_t headbase = ((size_t)(b * NH + h)) * TT * 64;

    auto load_kv = [&](int kt, int buf) {
#pragma unroll
        for (int i = 0; i < 8; i++) {
            int v = i * 128 + tid;
            int tile = v >> 9;
            int r = (v >> 3) & 63;
            int c8 = (v & 7) << 3;
            const __half* sp = tile ? Vf : Kf;
            uint32_t dst = sbase + (uint32_t)(FT * 2) * (1 + 2 * buf + tile)
                         + (uint32_t)(r * FSA + c8) * 2;
            CP_ASYNC16(dst, sp + headbase + (size_t)(kt * 64 + r) * 64 + c8);
        }
        CP_COMMIT();
    };

#pragma unroll
    for (int i = 0; i < 4; i++) {
        int v = i * 128 + tid;
        int r = v >> 3;
        int c8 = (v & 7) << 3;
        uint32_t dst = sbase + (uint32_t)(r * FSA + c8) * 2;
        CP_ASYNC16(dst, Qf + headbase + (size_t)(qt * 64 + r) * 64 + c8);
    }
    load_kv(0, 0);

    float m0 = -1e30f, m1 = -1e30f, l0 = 0.f, l1 = 0.f;
    float o[8][4];
#pragma unroll
    for (int nt = 0; nt < 8; nt++)
#pragma unroll
        for (int j = 0; j < 4; j++) o[nt][j] = 0.f;

    const int a_row = wrow + lj + ((li & 1) << 3);
    const int a_col = (li >> 1) << 3;
    const int b_row = li * 8 + lj;
    const int v_row = lj + ((li & 1) << 3);
    const int v_col = (lane >> 4) << 3;

    for (int kt = 0; kt <= qt; kt++) {
        const int buf = kt & 1;
        const bool pf = (kt + 1 <= qt);
        if (pf) load_kv(kt + 1, buf ^ 1);
        if (pf) { CP_WAIT1(); } else { CP_WAIT0(); }
        __syncthreads();

        const uint32_t oK = (uint32_t)(FT * 2) * (1 + 2 * buf);
        const uint32_t oV = oK + (uint32_t)(FT * 2);

        float s[8][4];
#pragma unroll
        for (int nt = 0; nt < 8; nt++)
#pragma unroll
            for (int j = 0; j < 4; j++) s[nt][j] = 0.f;

#pragma unroll
        for (int ks = 0; ks < 4; ks++) {
            const int k0 = ks * 16;
            unsigned a[4];
            uint32_t aa = sbase + (uint32_t)(a_row * FSA + k0 + a_col) * 2;
            ldsm4(a, aa);
#pragma unroll
            for (int nh = 0; nh < 2; nh++) {
                unsigned kfr[2][4];
#pragma unroll
                for (int kh = 0; kh < 2; kh++) {
                    uint32_t ba = sbase + oK + (uint32_t)((b_row + nh * 32) * FSA + k0 + kh * 8) * 2;
                    ldsm4(kfr[kh], ba);
                }
#pragma unroll
                for (int nt = 0; nt < 4; nt++)
                    mma_f16(s[nh * 4 + nt], a, kfr[0][nt], kfr[1][nt]);
            }
        }

        if (kt == qt) {
            int r0 = wrow + g, r1 = r0 + 8;
#pragma unroll
            for (int nt = 0; nt < 8; nt++) {
                int c0 = nt * 8 + 2 * t4, c1 = c0 + 1;
                if (c0 > r0) s[nt][0] = -1e30f;
                if (c1 > r0) s[nt][1] = -1e30f;
                if (c0 > r1) s[nt][2] = -1e30f;
                if (c1 > r1) s[nt][3] = -1e30f;
            }
        }

        float mx0 = -1e30f, mx1 = -1e30f;
#pragma unroll
        for (int nt = 0; nt < 8; nt++) {
            mx0 = fmaxf(mx0, fmaxf(s[nt][0], s[nt][1]));
            mx1 = fmaxf(mx1, fmaxf(s[nt][2], s[nt][3]));
        }
        mx0 = fmaxf(mx0, __shfl_xor_sync(0xffffffffu, mx0, 1));
        mx0 = fmaxf(mx0, __shfl_xor_sync(0xffffffffu, mx0, 2));
        mx1 = fmaxf(mx1, __shfl_xor_sync(0xffffffffu, mx1, 1));
        mx1 = fmaxf(mx1, __shfl_xor_sync(0xffffffffu, mx1, 2));

        float mn0 = fmaxf(m0, mx0), mn1 = fmaxf(m1, mx1);
        float alpha0 = __expf(m0 - mn0), alpha1 = __expf(m1 - mn1);
        m0 = mn0; m1 = mn1;

        float sum0 = 0.f, sum1 = 0.f;
#pragma unroll
        for (int nt = 0; nt < 8; nt++) {
            s[nt][0] = __expf(s[nt][0] - mn0);
            s[nt][1] = __expf(s[nt][1] - mn0);
            s[nt][2] = __expf(s[nt][2] - mn1);
            s[nt][3] = __expf(s[nt][3] - mn1);
            sum0 += s[nt][0] + s[nt][1];
            sum1 += s[nt][2] + s[nt][3];
        }
        sum0 += __shfl_xor_sync(0xffffffffu, sum0, 1);
        sum0 += __shfl_xor_sync(0xffffffffu, sum0, 2);
        sum1 += __shfl_xor_sync(0xffffffffu, sum1, 1);
        sum1 += __shfl_xor_sync(0xffffffffu, sum1, 2);
        l0 = l0 * alpha0 + sum0;
        l1 = l1 * alpha1 + sum1;

#pragma unroll
        for (int nt = 0; nt < 8; nt++) {
            o[nt][0] *= alpha0; o[nt][1] *= alpha0;
            o[nt][2] *= alpha1; o[nt][3] *= alpha1;
        }

#pragma unroll
        for (int ks = 0; ks < 4; ks++) {
            const int k0 = ks * 16;
            unsigned a[4];
            {
                float* p0 = s[2 * ks];
                float* p1 = s[2 * ks + 1];
                a[0] = pkH(p0[0], p0[1]);
                a[1] = pkH(p0[2], p0[3]);
                a[2] = pkH(p1[0], p1[1]);
                a[3] = pkH(p1[2], p1[3]);
            }
#pragma unroll
            for (int nh = 0; nh < 4; nh++) {
                uint32_t va = sbase + oV + (uint32_t)((k0 + v_row) * FSA + nh * 16 + v_col) * 2;
                unsigned vfr[4];
                ldsm4t(vfr, va);
                mma_f16(o[nh * 2],     a, vfr[0], vfr[1]);
                mma_f16(o[nh * 2 + 1], a, vfr[2], vfr[3]);
            }
        }
        __syncthreads();
    }

    float inv0 = 1.f / l0, inv1 = 1.f / l1;
    int row0 = qt * 64 + wrow + g;
    size_t base0 = ((size_t)(b * TT + row0)) * HIDDEN + h * 64;
    size_t base1 = base0 + 8 * HIDDEN;
#pragma unroll
    for (int nt = 0; nt < 8; nt++) {
        int c = nt * 8 + 2 * t4;
        __half2 p0 = __floats2half2_rn(o[nt][0] * inv0, o[nt][1] * inv0);
        __half2 p1 = __floats2half2_rn(o[nt][2] * inv1, o[nt][3] * inv1);
        *(unsigned*)&ctx[base0 + c] = *(unsigned*)&p0;
        *(unsigned*)&ctx[base1 + c] = *(unsigned*)&p1;
    }
}

// ---------------------------------------------------------------------------
extern "C" void kernel_launch(void* const* d_in, const int* in_sizes, int n_in,
                              void* d_out, int out_size)
{
    const float* hs    = (const float*)d_in[0];
    const float* cos_t = (const float*)d_in[1];
    const float* sin_t = (const float*)d_in[2];
    const float* wqkv  = (const float*)d_in[3];
    const float* wo    = (const float*)d_in[4];
    float* out = (float*)d_out;

    float* qkv = nullptr;
    __half *hs_f, *wq_h, *wo_h, *ctx, *qf, *kf, *vf;
    cudaGetSymbolAddress((void**)&qkv,  g_qkv);
    cudaGetSymbolAddress((void**)&hs_f, g_hs_f);
    cudaGetSymbolAddress((void**)&wq_h, g_wq_h);
    cudaGetSymbolAddress((void**)&wo_h, g_wo_h);
    cudaGetSymbolAddress((void**)&ctx,  g_ctx);
    cudaGetSymbolAddress((void**)&qf,   g_qf);
    cudaGetSymbolAddress((void**)&kf,   g_kf);
    cudaGetSymbolAddress((void**)&vf,   g_vf);

    // 0) converts (all plain fp16)
    conv_f16<<<MROWS * HIDDEN / 4 / 256, 256>>>(hs, hs_f, MROWS * HIDDEN / 4);
    conv_f16<<<QKV_O * HIDDEN / 4 / 256, 256>>>(wqkv, wq_h, QKV_O * HIDDEN / 4);
    conv_f16<<<HIDDEN * HIDDEN / 4 / 256, 256>>>(wo, wo_h, HIDDEN * HIDDEN / 4);

    cudaFuncSetAttribute(gemm_f16w64, cudaFuncAttributeMaxDynamicSharedMemorySize, 2 * BUFB1);

    // 1) QKV = hs @ wqkv^T  (single x1 GEMM, N=3072)
    gemm_f16w64<<<dim3(QKV_O / 128, MROWS / 128), 128, 2 * BUFB1>>>(
        hs_f, wq_h, qkv, QKV_O, HIDDEN);

    // 2) Fused RoPE + fp16 head-major layout
    rope_conv<<<(MROWS * 48 * 32) / 256, 256>>>(qkv, cos_t, sin_t, qf, kf, vf);

    // 3) Flash attention (fp16 x1 HMMA, double-buffered K/V)
    flash_attn_f16<<<dim3(TT / 64, NH, BB), 128>>>(qf, kf, vf, ctx);

    // 4) out = ctx @ wo^T (x1 weights)
    gemm_f16w64<<<dim3(HIDDEN / 128, MROWS / 128), 128, 2 * BUFB1>>>(
        ctx, wo_h, out, HIDDEN, HIDDEN);
}